// round 13
// baseline (speedup 1.0000x reference)
#include <cuda_runtime.h>

// ============================================================================
// DPSR: trilinear scatter -> 3D FFT -> spectral Poisson -> iFFT -> gather/norm
// res = 128, sigma = 2, eps = 1e-6, B = 1, N = 250000, F = 3
//
// Round 13: round-12 (proven 111.3us) + ONE change: in k_x_fused the partner
// rows (16..31) PREFETCH the A-rows' vz lines into smem at kernel entry,
// overlapping the strided global latency with the wv FFTs + combine. Rows
// 0..15's vz FFT then runs out of smem (no exposed global latency).
// ============================================================================

#define M3   2097152          // 128^3
#define FPI  3.14159265358979f
#define TP   130              // plane tile pitch in float2
#define PLANE_BYTES (128 * TP * sizeof(float2))

// ---- scratch (device globals; no allocation allowed) ----
__device__ float4 g_b_wv[M3/2];    // packed vx + i*vy (zy-transformed)
__device__ float4 g_b_Vz[M3/2];    // vz (zy-transformed)
__device__ float4 g_b_C[M3/2];     // chi_tilde (x-inverse applied)
__device__ float4 g_b_vzr[M3/4];   // scattered vz (real)
__device__ float4 g_b_chi[M3/4];   // chi_prime (real)
__device__ double g_stats[4];

#define g_wv  ((float2*)g_b_wv)
#define g_Vz  ((float2*)g_b_Vz)
#define g_C   ((float2*)g_b_C)
#define g_vzr ((float*)g_b_vzr)
#define g_chi ((float*)g_b_chi)

__device__ __forceinline__ float2 cadd(float2 a, float2 b){ return make_float2(a.x+b.x, a.y+b.y); }
__device__ __forceinline__ float2 csub(float2 a, float2 b){ return make_float2(a.x-b.x, a.y-b.y); }
__device__ __forceinline__ float2 cmul(float2 a, float2 b){
    return make_float2(a.x*b.x - a.y*b.y, a.x*b.y + a.y*b.x);
}

#define SWX(p) ((p) ^ ((((p) >> 4) & 7)))
#define XPITCH 136

__device__ __forceinline__ int rev3i(int t){
    return ((t & 1) << 2) | (t & 2) | ((t >> 2) & 1);
}
#define REV4(c) ((((c)&1)<<3) | (((c)&2)<<1) | (((c)&4)>>1) | (((c)&8)>>3))

// ============================================================================
// 128-pt radix-2 DIF FFT: 8 threads/line, 16 values/thread (p = t + 8m).
// Exchange buffer: xbase[SWX(p)*xs]. On return v[j] = result at p = 16t+j;
// true index k = 8*rev4(j)+rev3(t). Ends with __syncwarp (buffer reusable).
// ============================================================================
template<int DIR>
__device__ __forceinline__ void fft128_16(float2 v[16], const int t,
                                          float2* __restrict__ xbase, const int xs){
    const float D  = (float)DIR;
    const float SQ = 0.70710678118654752f;
    const float2 c8 = make_float2(0.92387953251128675f, D * 0.38268343236508977f);
    const float2 c4 = make_float2(SQ, D * SQ);

    float s, c;
    __sincosf(D * (FPI / 64.0f) * (float)t, &s, &c);
    const float2 wt  = make_float2(c, s);
    const float2 w2t = cmul(wt,  wt);
    const float2 w4t = cmul(w2t, w2t);
    const float2 w8t = cmul(w4t, w4t);

    // h=64
    {
        float2 w = wt;
        #pragma unroll
        for (int m = 0; m < 8; m++){
            float2 a = v[m], b = v[m+8];
            v[m]   = cadd(a, b);
            v[m+8] = cmul(csub(a, b), w);
            w = cmul(w, c8);
        }
    }
    // h=32
    {
        float2 w = w2t;
        #pragma unroll
        for (int q = 0; q < 4; q++){
            float2 a = v[q],   b = v[q+4];
            v[q]    = cadd(a, b);  v[q+4]  = cmul(csub(a, b), w);
            a = v[8+q]; b = v[12+q];
            v[8+q]  = cadd(a, b);  v[12+q] = cmul(csub(a, b), w);
            w = cmul(w, c4);
        }
    }
    // h=16
    {
        const float2 wa = w4t;
        const float2 wb = make_float2(-D * w4t.y, D * w4t.x);
        #pragma unroll
        for (int g = 0; g < 16; g += 4){
            float2 a = v[g],   b = v[g+2];
            v[g]   = cadd(a, b);  v[g+2] = cmul(csub(a, b), wa);
            a = v[g+1]; b = v[g+3];
            v[g+1] = cadd(a, b);  v[g+3] = cmul(csub(a, b), wb);
        }
    }
    // h=8
    {
        #pragma unroll
        for (int m = 0; m < 16; m += 2){
            float2 a = v[m], b = v[m+1];
            v[m]   = cadd(a, b);
            v[m+1] = cmul(csub(a, b), w8t);
        }
    }

    // exchange: re-own 16 consecutive positions [16t..16t+15]
    #pragma unroll
    for (int m = 0; m < 16; m++) xbase[SWX(t + 8*m) * xs] = v[m];
    __syncwarp();
    #pragma unroll
    for (int j = 0; j < 16; j++) v[j] = xbase[SWX(16*t + j) * xs];
    __syncwarp();   // callers may overwrite the buffer after return

    // h=4
    {
        const float2 w2 = make_float2(0.0f, D);
        const float2 w3 = make_float2(-SQ, D * SQ);
        #pragma unroll
        for (int g = 0; g < 16; g += 8){
            float2 a, b;
            a = v[g+0]; b = v[g+4]; v[g+0] = cadd(a,b); v[g+4] = csub(a,b);
            a = v[g+1]; b = v[g+5]; v[g+1] = cadd(a,b); v[g+5] = cmul(csub(a,b), c4);
            a = v[g+2]; b = v[g+6]; v[g+2] = cadd(a,b); v[g+6] = cmul(csub(a,b), w2);
            a = v[g+3]; b = v[g+7]; v[g+3] = cadd(a,b); v[g+7] = cmul(csub(a,b), w3);
        }
    }
    // h=2
    {
        #pragma unroll
        for (int g = 0; g < 16; g += 4){
            float2 a, b, d0;
            a = v[g+0]; b = v[g+2]; v[g+0] = cadd(a,b); v[g+2] = csub(a,b);
            a = v[g+1]; b = v[g+3]; v[g+1] = cadd(a,b);
            d0 = csub(a,b);
            v[g+3] = make_float2(-D * d0.y, D * d0.x);
        }
    }
    // h=1
    {
        #pragma unroll
        for (int g = 0; g < 16; g += 2){
            float2 a = v[g], b = v[g+1];
            v[g]   = cadd(a, b);
            v[g+1] = csub(a, b);
        }
    }
}

// ============================================================================
// Plane-fused forward z+y kernel (unchanged).
// ============================================================================

__global__ void __launch_bounds__(1024, 1) k_plane_zy_fwd(){
    extern __shared__ float2 tile[];   // 128 * TP
    const int lane = threadIdx.x & 31;
    const int w    = threadIdx.x >> 5;
    const int t    = lane & 7;
    const int sub  = lane >> 3;
    const int yline = (w & 3) + ((w >> 2) << 4) + (sub << 2);
    const int zline = (w << 2) + sub;
    const int plane = blockIdx.x << 14;

    float2 v[16];
    if (blockIdx.y == 0){
        #pragma unroll
        for (int m = 0; m < 16; m++) v[m] = g_wv[plane + yline*128 + t + 8*m];
    } else {
        #pragma unroll
        for (int m = 0; m < 16; m++) v[m] = make_float2(g_vzr[plane + yline*128 + t + 8*m], 0.0f);
    }
    fft128_16<-1>(v, t, tile + yline*TP, 1);
    {
        const int rt = rev3i(t);
        #pragma unroll
        for (int c = 0; c < 16; c++) tile[yline*TP + 8*c + rt] = v[REV4(c)];
    }
    __syncthreads();
    #pragma unroll
    for (int m = 0; m < 16; m++) v[m] = tile[(t + 8*m)*TP + zline];
    fft128_16<-1>(v, t, tile + zline, TP);
    {
        float2* gout = (blockIdx.y == 0) ? g_wv : g_Vz;
        const int rt = rev3i(t);
        #pragma unroll
        for (int c = 0; c < 16; c++)
            gout[plane + (8*c + rt)*128 + zline] = v[REV4(c)];
    }
}

// ============================================================================
// Inverse kz+ky plane kernel (unchanged, full).
// ============================================================================
__global__ void __launch_bounds__(1024, 1) k_plane_yz_inv(){
    extern __shared__ float2 tile[];   // 128 * TP
    const int lane = threadIdx.x & 31;
    const int w    = threadIdx.x >> 5;
    const int t    = lane & 7;
    const int sub  = lane >> 3;
    const int yline = (w & 3) + ((w >> 2) << 4) + (sub << 2);
    const int zline = (w << 2) + sub;
    const int plane = blockIdx.x << 14;

    float2 v[16];
    #pragma unroll
    for (int m = 0; m < 16; m++) v[m] = g_C[plane + yline*128 + t + 8*m];
    fft128_16<1>(v, t, tile + yline*TP, 1);
    {
        const int rt = rev3i(t);
        #pragma unroll
        for (int c = 0; c < 16; c++) tile[yline*TP + 8*c + rt] = v[REV4(c)];
    }
    __syncthreads();
    #pragma unroll
    for (int m = 0; m < 16; m++) v[m] = tile[(t + 8*m)*TP + zline];
    fft128_16<1>(v, t, tile + zline, TP);
    {
        const float sc = 1.0f / 2097152.0f;
        const int rt = rev3i(t);
        #pragma unroll
        for (int c = 0; c < 16; c++)
            g_chi[plane + (8*c + rt)*128 + zline] = v[REV4(c)].x * sc;
    }
}

// ============================================================================
// Mirror-paired fused x-phase. ALL 32 rows produce and store their chi line.
// Partner rows (16..31) use Hermitian symmetry for their Vz spectrum AND
// prefetch the A-rows' vz lines into sVz at kernel entry (position order),
// overlapping the strided global latency with the wv FFT + combine phases.
// ============================================================================
__global__ void __launch_bounds__(256, 2) k_x_fused(){
    __shared__ float2 xch[32][XPITCH];
    __shared__ float2 sW [32][XPITCH];
    __shared__ float  sS [32][XPITCH];
    __shared__ float2 sVz[16][XPITCH];
    const int t    = threadIdx.x & 7;
    const int row  = threadIdx.x >> 3;
    const int rt   = rev3i(t);
    const int r    = row & 15;
    const bool isB = row >= 16;
    const int kyA  = blockIdx.y;                 // 0..64
    const int kzA  = blockIdx.x * 16 + r;
    const int ky   = isB ? ((128 - kyA) & 127) : kyA;
    const int kz   = isB ? ((128 - kzA) & 127) : kzA;
    const int obase = ky * 128 + kz;
    const float uy = (float)(ky < 64 ? ky : ky - 128);
    const float uz = (float)(kz < 64 ? kz : kz - 128);

    float2 v[16];

    // (0) NEW: partner rows prefetch the paired A-row's vz line (position
    //     order) into sVz — latency overlapped with steps (a)-(c).
    if (isB){
        const int baseA = kyA * 128 + kzA;
        #pragma unroll
        for (int m = 0; m < 16; m++)
            sVz[r][t + 8*m] = g_Vz[baseA + (t + 8*m) * 16384];
    }

    // (a) own wv line: forward FFT -> sW[row][k]  (all 32 rows)
    #pragma unroll
    for (int m = 0; m < 16; m++) v[m] = g_wv[obase + (t + 8*m) * 16384];
    fft128_16<-1>(v, t, xch[row], 1);
    #pragma unroll
    for (int c = 0; c < 16; c++) sW[row][8*c + rt] = v[REV4(c)];
    __syncthreads();

    // (b) partial combine (ux,uy terms): A own (regs), Bm from partner row
    #pragma unroll
    for (int j = 0; j < 16; j++){
        const int k = 8 * REV4(j) + rt;
        float2 A  = v[j];
        float2 Bm = sW[row ^ 16][(128 - k) & 127];
        // Vx = (A + conj(Bm))/2 ; Vy = -i*(A - conj(Bm))/2
        float2 Vx = make_float2(0.5f * (A.x + Bm.x), 0.5f * (A.y - Bm.y));
        float2 Vy = make_float2(0.5f * (A.y + Bm.y), -0.5f * (A.x - Bm.x));
        float ux = (float)(k < 64 ? k : k - 128);
        float us = ux*ux + uy*uy + uz*uz;
        float gk = __expf(-us * (1.0f / 2048.0f));
        float s  = gk / (2.0f * FPI * (us + 1e-6f));
        sS[row][k] = s;
        float dre = ux*Vx.x + uy*Vy.x;
        float dim = ux*Vx.y + uy*Vy.y;
        v[j] = make_float2(s * dim, -s * dre);   // (-i)*(dre+i*dim)*s
    }
    __syncthreads();   // partner spectrum reads done; sVz prefetch visible

    // (c) park partial chi at k-order in own sW row
    #pragma unroll
    for (int c = 0; c < 16; c++) sW[row][8*c + rt] = v[REV4(c)];

    // (d) rows 0..15: vz FFT from smem (prefetched); park spectrum in sVz
    if (!isB){
        #pragma unroll
        for (int m = 0; m < 16; m++) v[m] = sVz[row][t + 8*m];
        fft128_16<-1>(v, t, xch[row], 1);
        #pragma unroll
        for (int c = 0; c < 16; c++) sVz[row][8*c + rt] = v[REV4(c)];
    }
    __syncthreads();   // Vz spectrum visible to partner rows

    // (e) final combine: chi(k) = partial(k) + s*uz*(-i*Vz(k))
    if (!isB){
        #pragma unroll
        for (int j = 0; j < 16; j++){
            const int k = 8 * REV4(j) + rt;
            float2 P   = sW[row][k];
            float  suz = sS[row][k] * uz;
            float2 Vz  = v[j];                      // own spectrum in regs
            v[j] = make_float2(P.x + suz * Vz.y, P.y - suz * Vz.x);
        }
    } else {
        #pragma unroll
        for (int j = 0; j < 16; j++){
            const int k = 8 * REV4(j) + rt;
            float2 P   = sW[row][k];
            float  suz = sS[row][k] * uz;
            float2 M   = sVz[row - 16][(128 - k) & 127];  // VzB = conj(M)
            // -i*conj(M) = (-M.y) + (-M.x) i
            v[j] = make_float2(P.x - suz * M.y, P.y - suz * M.x);
        }
    }

    // (f) reorder chi from k-order to position order via xch
    #pragma unroll
    for (int c = 0; c < 16; c++) xch[row][8*c + rt] = v[REV4(c)];
    __syncwarp();
    #pragma unroll
    for (int m = 0; m < 16; m++) v[m] = xch[row][t + 8*m];
    __syncwarp();

    // (g) inverse FFT along x, write g_C (all 32 rows store)
    fft128_16<1>(v, t, xch[row], 1);
    #pragma unroll
    for (int c = 0; c < 16; c++) g_C[obase + (8*c + rt) * 16384] = v[REV4(c)];
}

// ============================================================================
// Pipeline kernels (unchanged)
// ============================================================================

__global__ void k_init(){
    int i = blockIdx.x * 1024 + threadIdx.x;
    float4 z4 = make_float4(0.f, 0.f, 0.f, 0.f);
    if (i < 1048576) g_b_wv[i] = z4;
    else             g_b_vzr[i - 1048576] = z4;
    if (i < 4)       g_stats[i] = 0.0;
}

__device__ __forceinline__ void corners(float px, float py, float pz,
                                        int ix[2], int iy[2], int iz[2],
                                        float wx[2], float wy[2], float wz[2]){
    float prx = px * 128.0f, pry = py * 128.0f, prz = pz * 128.0f;
    float lox = floorf(prx), loy = floorf(pry), loz = floorf(prz);
    ix[0] = ((int)lox) & 127;  iy[0] = ((int)loy) & 127;  iz[0] = ((int)loz) & 127;
    ix[1] = ((int)ceilf(prx)) & 127;
    iy[1] = ((int)ceilf(pry)) & 127;
    iz[1] = ((int)ceilf(prz)) & 127;
    float fx = prx - lox, fy = pry - loy, fz = prz - loz;
    wx[0] = 1.0f - fx; wx[1] = fx;
    wy[0] = 1.0f - fy; wy[1] = fy;
    wz[0] = 1.0f - fz; wz[1] = fz;
}

__global__ void k_scatter(const float* __restrict__ pts,
                          const float* __restrict__ nrm, int N){
    int n = blockIdx.x * 256 + threadIdx.x;
    if (n >= N) return;
    float px = pts[3*n], py = pts[3*n+1], pz = pts[3*n+2];
    float nx = nrm[3*n], ny = nrm[3*n+1], nz = nrm[3*n+2];
    int ix[2], iy[2], iz[2]; float wx[2], wy[2], wz[2];
    corners(px, py, pz, ix, iy, iz, wx, wy, wz);
    #pragma unroll
    for (int c = 0; c < 8; c++){
        int a = (c >> 2) & 1, b = (c >> 1) & 1, d = c & 1;
        float w = wx[a] * wy[b] * wz[d];
        int idx = (ix[a] << 14) | (iy[b] << 7) | iz[d];
        atomicAdd(&g_wv[idx].x, w * nx);
        atomicAdd(&g_wv[idx].y, w * ny);
        atomicAdd(&g_vzr[idx],  w * nz);
    }
}

__global__ void k_interp(const float* __restrict__ pts, int N){
    int n = blockIdx.x * 256 + threadIdx.x;
    float acc = 0.0f;
    if (n < N){
        float px = pts[3*n], py = pts[3*n+1], pz = pts[3*n+2];
        int ix[2], iy[2], iz[2]; float wx[2], wy[2], wz[2];
        corners(px, py, pz, ix, iy, iz, wx, wy, wz);
        #pragma unroll
        for (int c = 0; c < 8; c++){
            int a = (c >> 2) & 1, b = (c >> 1) & 1, d = c & 1;
            float w = wx[a] * wy[b] * wz[d];
            int idx = (ix[a] << 14) | (iy[b] << 7) | iz[d];
            acc += w * g_chi[idx];
        }
    }
    #pragma unroll
    for (int o = 16; o > 0; o >>= 1)
        acc += __shfl_down_sync(0xffffffffu, acc, o);
    __shared__ float wsum[8];
    if ((threadIdx.x & 31) == 0) wsum[threadIdx.x >> 5] = acc;
    __syncthreads();
    if (threadIdx.x == 0){
        float s = 0.0f;
        #pragma unroll
        for (int i = 0; i < 8; i++) s += wsum[i];
        atomicAdd(&g_stats[0], (double)s);
    }
}

__global__ void k_finalize(int N){
    double mean = g_stats[0] / (double)N;
    double chi0 = (double)g_chi[0] - mean;
    g_stats[1] = mean;
    g_stats[2] = 0.5 / fabs(chi0);
}

__global__ void k_writeout(float4* __restrict__ out){
    int i = blockIdx.x * 256 + threadIdx.x;   // over M3/4
    float mean = (float)g_stats[1];
    float sc   = (float)g_stats[2];
    float4 c = g_b_chi[i];
    out[i] = make_float4(sc*(c.x-mean), sc*(c.y-mean), sc*(c.z-mean), sc*(c.w-mean));
}

// ============================================================================
// launch
// ============================================================================
extern "C" void kernel_launch(void* const* d_in, const int* in_sizes, int n_in,
                              void* d_out, int out_size){
    const float* pts = (const float*)d_in[0];
    const float* nrm = (const float*)d_in[1];
    const int N = in_sizes[0] / 3;

    cudaFuncSetAttribute(k_plane_zy_fwd, cudaFuncAttributeMaxDynamicSharedMemorySize,
                         (int)PLANE_BYTES);
    cudaFuncSetAttribute(k_plane_yz_inv, cudaFuncAttributeMaxDynamicSharedMemorySize,
                         (int)PLANE_BYTES);

    k_init<<<1536, 1024>>>();
    k_scatter<<<(N + 255) / 256, 256>>>(pts, nrm, N);
    // forward: fused z+y per plane (both fields)
    k_plane_zy_fwd<<<dim3(128, 2), 1024, PLANE_BYTES>>>();
    // mirror-paired fused x-phase (vz prefetched by partner rows)
    k_x_fused<<<dim3(8, 65), 256>>>();
    // inverse: fused kz+ky per plane (full)
    k_plane_yz_inv<<<128, 1024, PLANE_BYTES>>>();
    // gather, normalize, write
    k_interp<<<(N + 255) / 256, 256>>>(pts, N);
    k_finalize<<<1, 1>>>(N);
    k_writeout<<<2048, 256>>>((float4*)d_out);
}

// round 14
// speedup vs baseline: 1.0717x; 1.0717x over previous
#include <cuda_runtime.h>

// ============================================================================
// DPSR: trilinear scatter -> 3D FFT -> spectral Poisson -> iFFT -> gather/norm
// res = 128, sigma = 2, eps = 1e-6, B = 1, N = 250000, F = 3
//
// Round 14: round-12 configuration (proven 111.3us; prefetch reverted) +
// ONE change: k_plane_zy_fwd skips storing g_Vz lines with ky>64 — those
// planes are never read (x-phase uses Hermitian symmetry for ky>64).
// ============================================================================

#define M3   2097152          // 128^3
#define FPI  3.14159265358979f
#define TP   130              // plane tile pitch in float2
#define PLANE_BYTES (128 * TP * sizeof(float2))

// ---- scratch (device globals; no allocation allowed) ----
__device__ float4 g_b_wv[M3/2];    // packed vx + i*vy (zy-transformed)
__device__ float4 g_b_Vz[M3/2];    // vz (zy-transformed); ky<=64 planes only
__device__ float4 g_b_C[M3/2];     // chi_tilde (x-inverse applied)
__device__ float4 g_b_vzr[M3/4];   // scattered vz (real)
__device__ float4 g_b_chi[M3/4];   // chi_prime (real)
__device__ double g_stats[4];

#define g_wv  ((float2*)g_b_wv)
#define g_Vz  ((float2*)g_b_Vz)
#define g_C   ((float2*)g_b_C)
#define g_vzr ((float*)g_b_vzr)
#define g_chi ((float*)g_b_chi)

__device__ __forceinline__ float2 cadd(float2 a, float2 b){ return make_float2(a.x+b.x, a.y+b.y); }
__device__ __forceinline__ float2 csub(float2 a, float2 b){ return make_float2(a.x-b.x, a.y-b.y); }
__device__ __forceinline__ float2 cmul(float2 a, float2 b){
    return make_float2(a.x*b.x - a.y*b.y, a.x*b.y + a.y*b.x);
}

#define SWX(p) ((p) ^ ((((p) >> 4) & 7)))
#define XPITCH 136

__device__ __forceinline__ int rev3i(int t){
    return ((t & 1) << 2) | (t & 2) | ((t >> 2) & 1);
}
#define REV4(c) ((((c)&1)<<3) | (((c)&2)<<1) | (((c)&4)>>1) | (((c)&8)>>3))

// ============================================================================
// 128-pt radix-2 DIF FFT: 8 threads/line, 16 values/thread (p = t + 8m).
// Exchange buffer: xbase[SWX(p)*xs]. On return v[j] = result at p = 16t+j;
// true index k = 8*rev4(j)+rev3(t). Ends with __syncwarp (buffer reusable).
// ============================================================================
template<int DIR>
__device__ __forceinline__ void fft128_16(float2 v[16], const int t,
                                          float2* __restrict__ xbase, const int xs){
    const float D  = (float)DIR;
    const float SQ = 0.70710678118654752f;
    const float2 c8 = make_float2(0.92387953251128675f, D * 0.38268343236508977f);
    const float2 c4 = make_float2(SQ, D * SQ);

    float s, c;
    __sincosf(D * (FPI / 64.0f) * (float)t, &s, &c);
    const float2 wt  = make_float2(c, s);
    const float2 w2t = cmul(wt,  wt);
    const float2 w4t = cmul(w2t, w2t);
    const float2 w8t = cmul(w4t, w4t);

    // h=64
    {
        float2 w = wt;
        #pragma unroll
        for (int m = 0; m < 8; m++){
            float2 a = v[m], b = v[m+8];
            v[m]   = cadd(a, b);
            v[m+8] = cmul(csub(a, b), w);
            w = cmul(w, c8);
        }
    }
    // h=32
    {
        float2 w = w2t;
        #pragma unroll
        for (int q = 0; q < 4; q++){
            float2 a = v[q],   b = v[q+4];
            v[q]    = cadd(a, b);  v[q+4]  = cmul(csub(a, b), w);
            a = v[8+q]; b = v[12+q];
            v[8+q]  = cadd(a, b);  v[12+q] = cmul(csub(a, b), w);
            w = cmul(w, c4);
        }
    }
    // h=16
    {
        const float2 wa = w4t;
        const float2 wb = make_float2(-D * w4t.y, D * w4t.x);
        #pragma unroll
        for (int g = 0; g < 16; g += 4){
            float2 a = v[g],   b = v[g+2];
            v[g]   = cadd(a, b);  v[g+2] = cmul(csub(a, b), wa);
            a = v[g+1]; b = v[g+3];
            v[g+1] = cadd(a, b);  v[g+3] = cmul(csub(a, b), wb);
        }
    }
    // h=8
    {
        #pragma unroll
        for (int m = 0; m < 16; m += 2){
            float2 a = v[m], b = v[m+1];
            v[m]   = cadd(a, b);
            v[m+1] = cmul(csub(a, b), w8t);
        }
    }

    // exchange: re-own 16 consecutive positions [16t..16t+15]
    #pragma unroll
    for (int m = 0; m < 16; m++) xbase[SWX(t + 8*m) * xs] = v[m];
    __syncwarp();
    #pragma unroll
    for (int j = 0; j < 16; j++) v[j] = xbase[SWX(16*t + j) * xs];
    __syncwarp();   // callers may overwrite the buffer after return

    // h=4
    {
        const float2 w2 = make_float2(0.0f, D);
        const float2 w3 = make_float2(-SQ, D * SQ);
        #pragma unroll
        for (int g = 0; g < 16; g += 8){
            float2 a, b;
            a = v[g+0]; b = v[g+4]; v[g+0] = cadd(a,b); v[g+4] = csub(a,b);
            a = v[g+1]; b = v[g+5]; v[g+1] = cadd(a,b); v[g+5] = cmul(csub(a,b), c4);
            a = v[g+2]; b = v[g+6]; v[g+2] = cadd(a,b); v[g+6] = cmul(csub(a,b), w2);
            a = v[g+3]; b = v[g+7]; v[g+3] = cadd(a,b); v[g+7] = cmul(csub(a,b), w3);
        }
    }
    // h=2
    {
        #pragma unroll
        for (int g = 0; g < 16; g += 4){
            float2 a, b, d0;
            a = v[g+0]; b = v[g+2]; v[g+0] = cadd(a,b); v[g+2] = csub(a,b);
            a = v[g+1]; b = v[g+3]; v[g+1] = cadd(a,b);
            d0 = csub(a,b);
            v[g+3] = make_float2(-D * d0.y, D * d0.x);
        }
    }
    // h=1
    {
        #pragma unroll
        for (int g = 0; g < 16; g += 2){
            float2 a = v[g], b = v[g+1];
            v[g]   = cadd(a, b);
            v[g+1] = csub(a, b);
        }
    }
}

// ============================================================================
// Plane-fused forward z+y kernel. vz branch stores only ky<=64 output lines
// (g_Vz ky>64 planes are never read downstream).
// ============================================================================

__global__ void __launch_bounds__(1024, 1) k_plane_zy_fwd(){
    extern __shared__ float2 tile[];   // 128 * TP
    const int lane = threadIdx.x & 31;
    const int w    = threadIdx.x >> 5;
    const int t    = lane & 7;
    const int sub  = lane >> 3;
    const int yline = (w & 3) + ((w >> 2) << 4) + (sub << 2);
    const int zline = (w << 2) + sub;
    const int plane = blockIdx.x << 14;

    float2 v[16];
    if (blockIdx.y == 0){
        #pragma unroll
        for (int m = 0; m < 16; m++) v[m] = g_wv[plane + yline*128 + t + 8*m];
    } else {
        #pragma unroll
        for (int m = 0; m < 16; m++) v[m] = make_float2(g_vzr[plane + yline*128 + t + 8*m], 0.0f);
    }
    fft128_16<-1>(v, t, tile + yline*TP, 1);
    {
        const int rt = rev3i(t);
        #pragma unroll
        for (int c = 0; c < 16; c++) tile[yline*TP + 8*c + rt] = v[REV4(c)];
    }
    __syncthreads();
    #pragma unroll
    for (int m = 0; m < 16; m++) v[m] = tile[(t + 8*m)*TP + zline];
    fft128_16<-1>(v, t, tile + zline, TP);
    {
        const int rt = rev3i(t);
        if (blockIdx.y == 0){
            #pragma unroll
            for (int c = 0; c < 16; c++)
                g_wv[plane + (8*c + rt)*128 + zline] = v[REV4(c)];
        } else {
            #pragma unroll
            for (int c = 0; c < 16; c++){
                int kyOut = 8*c + rt;
                if (kyOut <= 64)
                    g_Vz[plane + kyOut*128 + zline] = v[REV4(c)];
            }
        }
    }
}

// ============================================================================
// Inverse kz+ky plane kernel (full).
// ============================================================================
__global__ void __launch_bounds__(1024, 1) k_plane_yz_inv(){
    extern __shared__ float2 tile[];   // 128 * TP
    const int lane = threadIdx.x & 31;
    const int w    = threadIdx.x >> 5;
    const int t    = lane & 7;
    const int sub  = lane >> 3;
    const int yline = (w & 3) + ((w >> 2) << 4) + (sub << 2);
    const int zline = (w << 2) + sub;
    const int plane = blockIdx.x << 14;

    float2 v[16];
    #pragma unroll
    for (int m = 0; m < 16; m++) v[m] = g_C[plane + yline*128 + t + 8*m];
    fft128_16<1>(v, t, tile + yline*TP, 1);
    {
        const int rt = rev3i(t);
        #pragma unroll
        for (int c = 0; c < 16; c++) tile[yline*TP + 8*c + rt] = v[REV4(c)];
    }
    __syncthreads();
    #pragma unroll
    for (int m = 0; m < 16; m++) v[m] = tile[(t + 8*m)*TP + zline];
    fft128_16<1>(v, t, tile + zline, TP);
    {
        const float sc = 1.0f / 2097152.0f;
        const int rt = rev3i(t);
        #pragma unroll
        for (int c = 0; c < 16; c++)
            g_chi[plane + (8*c + rt)*128 + zline] = v[REV4(c)].x * sc;
    }
}

// ============================================================================
// Mirror-paired fused x-phase (round-12 verbatim). ALL 32 rows produce and
// store their chi line; partner rows (16..31) get their Vz spectrum via
// Hermitian symmetry (Vz is the transform of a real field) from smem.
// ============================================================================
__global__ void __launch_bounds__(256, 2) k_x_fused(){
    __shared__ float2 xch[32][XPITCH];
    __shared__ float2 sW [32][XPITCH];
    __shared__ float  sS [32][XPITCH];
    __shared__ float2 sVz[16][XPITCH];
    const int t    = threadIdx.x & 7;
    const int row  = threadIdx.x >> 3;
    const int rt   = rev3i(t);
    const int r    = row & 15;
    const bool isB = row >= 16;
    const int kyA  = blockIdx.y;                 // 0..64
    const int kzA  = blockIdx.x * 16 + r;
    const int ky   = isB ? ((128 - kyA) & 127) : kyA;
    const int kz   = isB ? ((128 - kzA) & 127) : kzA;
    const int obase = ky * 128 + kz;
    const float uy = (float)(ky < 64 ? ky : ky - 128);
    const float uz = (float)(kz < 64 ? kz : kz - 128);

    float2 v[16];

    // (a) own wv line: forward FFT -> sW[row][k]  (all 32 rows)
    #pragma unroll
    for (int m = 0; m < 16; m++) v[m] = g_wv[obase + (t + 8*m) * 16384];
    fft128_16<-1>(v, t, xch[row], 1);
    #pragma unroll
    for (int c = 0; c < 16; c++) sW[row][8*c + rt] = v[REV4(c)];
    __syncthreads();

    // (b) partial combine (ux,uy terms): A own (regs), Bm from partner row
    #pragma unroll
    for (int j = 0; j < 16; j++){
        const int k = 8 * REV4(j) + rt;
        float2 A  = v[j];
        float2 Bm = sW[row ^ 16][(128 - k) & 127];
        // Vx = (A + conj(Bm))/2 ; Vy = -i*(A - conj(Bm))/2
        float2 Vx = make_float2(0.5f * (A.x + Bm.x), 0.5f * (A.y - Bm.y));
        float2 Vy = make_float2(0.5f * (A.y + Bm.y), -0.5f * (A.x - Bm.x));
        float ux = (float)(k < 64 ? k : k - 128);
        float us = ux*ux + uy*uy + uz*uz;
        float gk = __expf(-us * (1.0f / 2048.0f));
        float s  = gk / (2.0f * FPI * (us + 1e-6f));
        sS[row][k] = s;
        float dre = ux*Vx.x + uy*Vy.x;
        float dim = ux*Vx.y + uy*Vy.y;
        v[j] = make_float2(s * dim, -s * dre);   // (-i)*(dre+i*dim)*s
    }
    __syncthreads();   // all partner spectrum reads done before overwriting sW

    // (c) park partial chi at k-order in own sW row
    #pragma unroll
    for (int c = 0; c < 16; c++) sW[row][8*c + rt] = v[REV4(c)];

    // (d) rows 0..15: vz line forward FFT -> regs; park spectrum for partners
    if (!isB){
        #pragma unroll
        for (int m = 0; m < 16; m++) v[m] = g_Vz[obase + (t + 8*m) * 16384];
        fft128_16<-1>(v, t, xch[row], 1);
        #pragma unroll
        for (int c = 0; c < 16; c++) sVz[row][8*c + rt] = v[REV4(c)];
    }
    __syncthreads();   // sVz visible to partner rows

    // (e) final combine: chi(k) = partial(k) + s*uz*(-i*Vz(k))
    if (!isB){
        #pragma unroll
        for (int j = 0; j < 16; j++){
            const int k = 8 * REV4(j) + rt;
            float2 P   = sW[row][k];
            float  suz = sS[row][k] * uz;
            float2 Vz  = v[j];                      // own spectrum in regs
            v[j] = make_float2(P.x + suz * Vz.y, P.y - suz * Vz.x);
        }
    } else {
        #pragma unroll
        for (int j = 0; j < 16; j++){
            const int k = 8 * REV4(j) + rt;
            float2 P   = sW[row][k];
            float  suz = sS[row][k] * uz;
            float2 M   = sVz[row - 16][(128 - k) & 127];  // VzB = conj(M)
            // -i*conj(M) = (-M.y) + (-M.x) i
            v[j] = make_float2(P.x - suz * M.y, P.y - suz * M.x);
        }
    }

    // (f) reorder chi from k-order to position order via xch
    #pragma unroll
    for (int c = 0; c < 16; c++) xch[row][8*c + rt] = v[REV4(c)];
    __syncwarp();
    #pragma unroll
    for (int m = 0; m < 16; m++) v[m] = xch[row][t + 8*m];
    __syncwarp();

    // (g) inverse FFT along x, write g_C (all 32 rows store)
    fft128_16<1>(v, t, xch[row], 1);
    #pragma unroll
    for (int c = 0; c < 16; c++) g_C[obase + (8*c + rt) * 16384] = v[REV4(c)];
}

// ============================================================================
// Pipeline kernels (unchanged)
// ============================================================================

__global__ void k_init(){
    int i = blockIdx.x * 1024 + threadIdx.x;
    float4 z4 = make_float4(0.f, 0.f, 0.f, 0.f);
    if (i < 1048576) g_b_wv[i] = z4;
    else             g_b_vzr[i - 1048576] = z4;
    if (i < 4)       g_stats[i] = 0.0;
}

__device__ __forceinline__ void corners(float px, float py, float pz,
                                        int ix[2], int iy[2], int iz[2],
                                        float wx[2], float wy[2], float wz[2]){
    float prx = px * 128.0f, pry = py * 128.0f, prz = pz * 128.0f;
    float lox = floorf(prx), loy = floorf(pry), loz = floorf(prz);
    ix[0] = ((int)lox) & 127;  iy[0] = ((int)loy) & 127;  iz[0] = ((int)loz) & 127;
    ix[1] = ((int)ceilf(prx)) & 127;
    iy[1] = ((int)ceilf(pry)) & 127;
    iz[1] = ((int)ceilf(prz)) & 127;
    float fx = prx - lox, fy = pry - loy, fz = prz - loz;
    wx[0] = 1.0f - fx; wx[1] = fx;
    wy[0] = 1.0f - fy; wy[1] = fy;
    wz[0] = 1.0f - fz; wz[1] = fz;
}

__global__ void k_scatter(const float* __restrict__ pts,
                          const float* __restrict__ nrm, int N){
    int n = blockIdx.x * 256 + threadIdx.x;
    if (n >= N) return;
    float px = pts[3*n], py = pts[3*n+1], pz = pts[3*n+2];
    float nx = nrm[3*n], ny = nrm[3*n+1], nz = nrm[3*n+2];
    int ix[2], iy[2], iz[2]; float wx[2], wy[2], wz[2];
    corners(px, py, pz, ix, iy, iz, wx, wy, wz);
    #pragma unroll
    for (int c = 0; c < 8; c++){
        int a = (c >> 2) & 1, b = (c >> 1) & 1, d = c & 1;
        float w = wx[a] * wy[b] * wz[d];
        int idx = (ix[a] << 14) | (iy[b] << 7) | iz[d];
        atomicAdd(&g_wv[idx].x, w * nx);
        atomicAdd(&g_wv[idx].y, w * ny);
        atomicAdd(&g_vzr[idx],  w * nz);
    }
}

__global__ void k_interp(const float* __restrict__ pts, int N){
    int n = blockIdx.x * 256 + threadIdx.x;
    float acc = 0.0f;
    if (n < N){
        float px = pts[3*n], py = pts[3*n+1], pz = pts[3*n+2];
        int ix[2], iy[2], iz[2]; float wx[2], wy[2], wz[2];
        corners(px, py, pz, ix, iy, iz, wx, wy, wz);
        #pragma unroll
        for (int c = 0; c < 8; c++){
            int a = (c >> 2) & 1, b = (c >> 1) & 1, d = c & 1;
            float w = wx[a] * wy[b] * wz[d];
            int idx = (ix[a] << 14) | (iy[b] << 7) | iz[d];
            acc += w * g_chi[idx];
        }
    }
    #pragma unroll
    for (int o = 16; o > 0; o >>= 1)
        acc += __shfl_down_sync(0xffffffffu, acc, o);
    __shared__ float wsum[8];
    if ((threadIdx.x & 31) == 0) wsum[threadIdx.x >> 5] = acc;
    __syncthreads();
    if (threadIdx.x == 0){
        float s = 0.0f;
        #pragma unroll
        for (int i = 0; i < 8; i++) s += wsum[i];
        atomicAdd(&g_stats[0], (double)s);
    }
}

__global__ void k_finalize(int N){
    double mean = g_stats[0] / (double)N;
    double chi0 = (double)g_chi[0] - mean;
    g_stats[1] = mean;
    g_stats[2] = 0.5 / fabs(chi0);
}

__global__ void k_writeout(float4* __restrict__ out){
    int i = blockIdx.x * 256 + threadIdx.x;   // over M3/4
    float mean = (float)g_stats[1];
    float sc   = (float)g_stats[2];
    float4 c = g_b_chi[i];
    out[i] = make_float4(sc*(c.x-mean), sc*(c.y-mean), sc*(c.z-mean), sc*(c.w-mean));
}

// ============================================================================
// launch
// ============================================================================
extern "C" void kernel_launch(void* const* d_in, const int* in_sizes, int n_in,
                              void* d_out, int out_size){
    const float* pts = (const float*)d_in[0];
    const float* nrm = (const float*)d_in[1];
    const int N = in_sizes[0] / 3;

    cudaFuncSetAttribute(k_plane_zy_fwd, cudaFuncAttributeMaxDynamicSharedMemorySize,
                         (int)PLANE_BYTES);
    cudaFuncSetAttribute(k_plane_yz_inv, cudaFuncAttributeMaxDynamicSharedMemorySize,
                         (int)PLANE_BYTES);

    k_init<<<1536, 1024>>>();
    k_scatter<<<(N + 255) / 256, 256>>>(pts, nrm, N);
    // forward: fused z+y per plane (both fields; vz stores ky<=64 only)
    k_plane_zy_fwd<<<dim3(128, 2), 1024, PLANE_BYTES>>>();
    // mirror-paired fused x-phase (Vz shared via Hermitian symmetry)
    k_x_fused<<<dim3(8, 65), 256>>>();
    // inverse: fused kz+ky per plane (full)
    k_plane_yz_inv<<<128, 1024, PLANE_BYTES>>>();
    // gather, normalize, write
    k_interp<<<(N + 255) / 256, 256>>>(pts, N);
    k_finalize<<<1, 1>>>(N);
    k_writeout<<<2048, 256>>>((float4*)d_out);
}

// round 15
// speedup vs baseline: 1.1583x; 1.0808x over previous
#include <cuda_runtime.h>

// ============================================================================
// DPSR: trilinear scatter -> 3D FFT -> spectral Poisson -> iFFT -> gather/norm
// res = 128, sigma = 2, eps = 1e-6, B = 1, N = 250000, F = 3
//
// Round 15: (1) vz plane-pairing in k_plane_zy_fwd — planes x and x+64 packed
// as one complex plane, Hermitian-unpacked from the smem tile (vz FFT work
// halves; grid 256->192). (2) float2 vector atomics in scatter (24->16 REDs).
// ============================================================================

#define M3   2097152          // 128^3
#define FPI  3.14159265358979f
#define TP   130              // plane tile pitch in float2
#define PLANE_BYTES (128 * TP * sizeof(float2))

// ---- scratch (device globals; no allocation allowed) ----
__device__ float4 g_b_wv[M3/2];    // packed vx + i*vy (zy-transformed)
__device__ float4 g_b_Vz[M3/2];    // vz (zy-transformed); ky<=64 planes only
__device__ float4 g_b_C[M3/2];     // chi_tilde (x-inverse applied)
__device__ float4 g_b_vzr[M3/4];   // scattered vz (real)
__device__ float4 g_b_chi[M3/4];   // chi_prime (real)
__device__ double g_stats[4];

#define g_wv  ((float2*)g_b_wv)
#define g_Vz  ((float2*)g_b_Vz)
#define g_C   ((float2*)g_b_C)
#define g_vzr ((float*)g_b_vzr)
#define g_chi ((float*)g_b_chi)

__device__ __forceinline__ float2 cadd(float2 a, float2 b){ return make_float2(a.x+b.x, a.y+b.y); }
__device__ __forceinline__ float2 csub(float2 a, float2 b){ return make_float2(a.x-b.x, a.y-b.y); }
__device__ __forceinline__ float2 cmul(float2 a, float2 b){
    return make_float2(a.x*b.x - a.y*b.y, a.x*b.y + a.y*b.x);
}

#define SWX(p) ((p) ^ ((((p) >> 4) & 7)))
#define XPITCH 136

__device__ __forceinline__ int rev3i(int t){
    return ((t & 1) << 2) | (t & 2) | ((t >> 2) & 1);
}
#define REV4(c) ((((c)&1)<<3) | (((c)&2)<<1) | (((c)&4)>>1) | (((c)&8)>>3))

// ============================================================================
// 128-pt radix-2 DIF FFT: 8 threads/line, 16 values/thread (p = t + 8m).
// Exchange buffer: xbase[SWX(p)*xs]. On return v[j] = result at p = 16t+j;
// true index k = 8*rev4(j)+rev3(t). Ends with __syncwarp (buffer reusable).
// ============================================================================
template<int DIR>
__device__ __forceinline__ void fft128_16(float2 v[16], const int t,
                                          float2* __restrict__ xbase, const int xs){
    const float D  = (float)DIR;
    const float SQ = 0.70710678118654752f;
    const float2 c8 = make_float2(0.92387953251128675f, D * 0.38268343236508977f);
    const float2 c4 = make_float2(SQ, D * SQ);

    float s, c;
    __sincosf(D * (FPI / 64.0f) * (float)t, &s, &c);
    const float2 wt  = make_float2(c, s);
    const float2 w2t = cmul(wt,  wt);
    const float2 w4t = cmul(w2t, w2t);
    const float2 w8t = cmul(w4t, w4t);

    // h=64
    {
        float2 w = wt;
        #pragma unroll
        for (int m = 0; m < 8; m++){
            float2 a = v[m], b = v[m+8];
            v[m]   = cadd(a, b);
            v[m+8] = cmul(csub(a, b), w);
            w = cmul(w, c8);
        }
    }
    // h=32
    {
        float2 w = w2t;
        #pragma unroll
        for (int q = 0; q < 4; q++){
            float2 a = v[q],   b = v[q+4];
            v[q]    = cadd(a, b);  v[q+4]  = cmul(csub(a, b), w);
            a = v[8+q]; b = v[12+q];
            v[8+q]  = cadd(a, b);  v[12+q] = cmul(csub(a, b), w);
            w = cmul(w, c4);
        }
    }
    // h=16
    {
        const float2 wa = w4t;
        const float2 wb = make_float2(-D * w4t.y, D * w4t.x);
        #pragma unroll
        for (int g = 0; g < 16; g += 4){
            float2 a = v[g],   b = v[g+2];
            v[g]   = cadd(a, b);  v[g+2] = cmul(csub(a, b), wa);
            a = v[g+1]; b = v[g+3];
            v[g+1] = cadd(a, b);  v[g+3] = cmul(csub(a, b), wb);
        }
    }
    // h=8
    {
        #pragma unroll
        for (int m = 0; m < 16; m += 2){
            float2 a = v[m], b = v[m+1];
            v[m]   = cadd(a, b);
            v[m+1] = cmul(csub(a, b), w8t);
        }
    }

    // exchange: re-own 16 consecutive positions [16t..16t+15]
    #pragma unroll
    for (int m = 0; m < 16; m++) xbase[SWX(t + 8*m) * xs] = v[m];
    __syncwarp();
    #pragma unroll
    for (int j = 0; j < 16; j++) v[j] = xbase[SWX(16*t + j) * xs];
    __syncwarp();   // callers may overwrite the buffer after return

    // h=4
    {
        const float2 w2 = make_float2(0.0f, D);
        const float2 w3 = make_float2(-SQ, D * SQ);
        #pragma unroll
        for (int g = 0; g < 16; g += 8){
            float2 a, b;
            a = v[g+0]; b = v[g+4]; v[g+0] = cadd(a,b); v[g+4] = csub(a,b);
            a = v[g+1]; b = v[g+5]; v[g+1] = cadd(a,b); v[g+5] = cmul(csub(a,b), c4);
            a = v[g+2]; b = v[g+6]; v[g+2] = cadd(a,b); v[g+6] = cmul(csub(a,b), w2);
            a = v[g+3]; b = v[g+7]; v[g+3] = cadd(a,b); v[g+7] = cmul(csub(a,b), w3);
        }
    }
    // h=2
    {
        #pragma unroll
        for (int g = 0; g < 16; g += 4){
            float2 a, b, d0;
            a = v[g+0]; b = v[g+2]; v[g+0] = cadd(a,b); v[g+2] = csub(a,b);
            a = v[g+1]; b = v[g+3]; v[g+1] = cadd(a,b);
            d0 = csub(a,b);
            v[g+3] = make_float2(-D * d0.y, D * d0.x);
        }
    }
    // h=1
    {
        #pragma unroll
        for (int g = 0; g < 16; g += 2){
            float2 a = v[g], b = v[g+1];
            v[g]   = cadd(a, b);
            v[g+1] = csub(a, b);
        }
    }
}

// ============================================================================
// Plane-fused forward z+y kernel.
// blocks 0..127  : wv plane x = bid (in place).
// blocks 128..191: vz planes x1 = bid-128, x2 = x1+64, packed as
//                  P = vz(x1) + i*vz(x2); after z+y FFT the tile holds the
//                  full plane spectrum; Hermitian unpack -> g_Vz (ky<=64).
// ============================================================================
__global__ void __launch_bounds__(1024, 1) k_plane_zy_fwd(){
    extern __shared__ float2 tile[];   // 128 * TP
    const int lane = threadIdx.x & 31;
    const int w    = threadIdx.x >> 5;
    const int t    = lane & 7;
    const int sub  = lane >> 3;
    const int yline = (w & 3) + ((w >> 2) << 4) + (sub << 2);
    const int zline = (w << 2) + sub;
    const int bid  = blockIdx.x;
    const bool isWV = (bid < 128);
    const int x1   = isWV ? bid : (bid - 128);
    const int x2   = x1 + 64;          // vz partner plane
    const int plane = x1 << 14;

    float2 v[16];
    if (isWV){
        #pragma unroll
        for (int m = 0; m < 16; m++) v[m] = g_wv[plane + yline*128 + t + 8*m];
    } else {
        #pragma unroll
        for (int m = 0; m < 16; m++)
            v[m] = make_float2(g_vzr[plane + yline*128 + t + 8*m],
                               g_vzr[(x2 << 14) + yline*128 + t + 8*m]);
    }
    fft128_16<-1>(v, t, tile + yline*TP, 1);
    {
        const int rt = rev3i(t);
        #pragma unroll
        for (int c = 0; c < 16; c++) tile[yline*TP + 8*c + rt] = v[REV4(c)];
    }
    __syncthreads();
    #pragma unroll
    for (int m = 0; m < 16; m++) v[m] = tile[(t + 8*m)*TP + zline];
    fft128_16<-1>(v, t, tile + zline, TP);

    if (isWV){
        const int rt = rev3i(t);
        #pragma unroll
        for (int c = 0; c < 16; c++)
            g_wv[plane + (8*c + rt)*128 + zline] = v[REV4(c)];
    } else {
        // park y-FFT results into own column (position = ky), then unpack
        const int rt = rev3i(t);
        #pragma unroll
        for (int c = 0; c < 16; c++)
            tile[(8*c + rt)*TP + zline] = v[REV4(c)];
        __syncthreads();
        // Hermitian unpack: Vz1 = (A + conj(Bm))/2, Vz2 = -i*(A - conj(Bm))/2
        const int base1 = x1 << 14, base2 = x2 << 14;
        for (int i = threadIdx.x; i < 65 * 128; i += 1024){
            int ky = i >> 7, kz = i & 127;
            float2 A  = tile[ky * TP + kz];
            float2 Bm = tile[((128 - ky) & 127) * TP + ((128 - kz) & 127)];
            float2 V1 = make_float2(0.5f * (A.x + Bm.x), 0.5f * (A.y - Bm.y));
            float2 V2 = make_float2(0.5f * (A.y + Bm.y), -0.5f * (A.x - Bm.x));
            g_Vz[base1 + ky * 128 + kz] = V1;
            g_Vz[base2 + ky * 128 + kz] = V2;
        }
    }
}

// ============================================================================
// Inverse kz+ky plane kernel (full, unchanged).
// ============================================================================
__global__ void __launch_bounds__(1024, 1) k_plane_yz_inv(){
    extern __shared__ float2 tile[];   // 128 * TP
    const int lane = threadIdx.x & 31;
    const int w    = threadIdx.x >> 5;
    const int t    = lane & 7;
    const int sub  = lane >> 3;
    const int yline = (w & 3) + ((w >> 2) << 4) + (sub << 2);
    const int zline = (w << 2) + sub;
    const int plane = blockIdx.x << 14;

    float2 v[16];
    #pragma unroll
    for (int m = 0; m < 16; m++) v[m] = g_C[plane + yline*128 + t + 8*m];
    fft128_16<1>(v, t, tile + yline*TP, 1);
    {
        const int rt = rev3i(t);
        #pragma unroll
        for (int c = 0; c < 16; c++) tile[yline*TP + 8*c + rt] = v[REV4(c)];
    }
    __syncthreads();
    #pragma unroll
    for (int m = 0; m < 16; m++) v[m] = tile[(t + 8*m)*TP + zline];
    fft128_16<1>(v, t, tile + zline, TP);
    {
        const float sc = 1.0f / 2097152.0f;
        const int rt = rev3i(t);
        #pragma unroll
        for (int c = 0; c < 16; c++)
            g_chi[plane + (8*c + rt)*128 + zline] = v[REV4(c)].x * sc;
    }
}

// ============================================================================
// Mirror-paired fused x-phase (round-12 verbatim). ALL 32 rows produce and
// store their chi line; partner rows (16..31) get their Vz spectrum via
// Hermitian symmetry (Vz is the transform of a real field) from smem.
// ============================================================================
__global__ void __launch_bounds__(256, 2) k_x_fused(){
    __shared__ float2 xch[32][XPITCH];
    __shared__ float2 sW [32][XPITCH];
    __shared__ float  sS [32][XPITCH];
    __shared__ float2 sVz[16][XPITCH];
    const int t    = threadIdx.x & 7;
    const int row  = threadIdx.x >> 3;
    const int rt   = rev3i(t);
    const int r    = row & 15;
    const bool isB = row >= 16;
    const int kyA  = blockIdx.y;                 // 0..64
    const int kzA  = blockIdx.x * 16 + r;
    const int ky   = isB ? ((128 - kyA) & 127) : kyA;
    const int kz   = isB ? ((128 - kzA) & 127) : kzA;
    const int obase = ky * 128 + kz;
    const float uy = (float)(ky < 64 ? ky : ky - 128);
    const float uz = (float)(kz < 64 ? kz : kz - 128);

    float2 v[16];

    // (a) own wv line: forward FFT -> sW[row][k]  (all 32 rows)
    #pragma unroll
    for (int m = 0; m < 16; m++) v[m] = g_wv[obase + (t + 8*m) * 16384];
    fft128_16<-1>(v, t, xch[row], 1);
    #pragma unroll
    for (int c = 0; c < 16; c++) sW[row][8*c + rt] = v[REV4(c)];
    __syncthreads();

    // (b) partial combine (ux,uy terms): A own (regs), Bm from partner row
    #pragma unroll
    for (int j = 0; j < 16; j++){
        const int k = 8 * REV4(j) + rt;
        float2 A  = v[j];
        float2 Bm = sW[row ^ 16][(128 - k) & 127];
        // Vx = (A + conj(Bm))/2 ; Vy = -i*(A - conj(Bm))/2
        float2 Vx = make_float2(0.5f * (A.x + Bm.x), 0.5f * (A.y - Bm.y));
        float2 Vy = make_float2(0.5f * (A.y + Bm.y), -0.5f * (A.x - Bm.x));
        float ux = (float)(k < 64 ? k : k - 128);
        float us = ux*ux + uy*uy + uz*uz;
        float gk = __expf(-us * (1.0f / 2048.0f));
        float s  = gk / (2.0f * FPI * (us + 1e-6f));
        sS[row][k] = s;
        float dre = ux*Vx.x + uy*Vy.x;
        float dim = ux*Vx.y + uy*Vy.y;
        v[j] = make_float2(s * dim, -s * dre);   // (-i)*(dre+i*dim)*s
    }
    __syncthreads();   // all partner spectrum reads done before overwriting sW

    // (c) park partial chi at k-order in own sW row
    #pragma unroll
    for (int c = 0; c < 16; c++) sW[row][8*c + rt] = v[REV4(c)];

    // (d) rows 0..15: vz line forward FFT -> regs; park spectrum for partners
    if (!isB){
        #pragma unroll
        for (int m = 0; m < 16; m++) v[m] = g_Vz[obase + (t + 8*m) * 16384];
        fft128_16<-1>(v, t, xch[row], 1);
        #pragma unroll
        for (int c = 0; c < 16; c++) sVz[row][8*c + rt] = v[REV4(c)];
    }
    __syncthreads();   // sVz visible to partner rows

    // (e) final combine: chi(k) = partial(k) + s*uz*(-i*Vz(k))
    if (!isB){
        #pragma unroll
        for (int j = 0; j < 16; j++){
            const int k = 8 * REV4(j) + rt;
            float2 P   = sW[row][k];
            float  suz = sS[row][k] * uz;
            float2 Vz  = v[j];                      // own spectrum in regs
            v[j] = make_float2(P.x + suz * Vz.y, P.y - suz * Vz.x);
        }
    } else {
        #pragma unroll
        for (int j = 0; j < 16; j++){
            const int k = 8 * REV4(j) + rt;
            float2 P   = sW[row][k];
            float  suz = sS[row][k] * uz;
            float2 M   = sVz[row - 16][(128 - k) & 127];  // VzB = conj(M)
            // -i*conj(M) = (-M.y) + (-M.x) i
            v[j] = make_float2(P.x - suz * M.y, P.y - suz * M.x);
        }
    }

    // (f) reorder chi from k-order to position order via xch
    #pragma unroll
    for (int c = 0; c < 16; c++) xch[row][8*c + rt] = v[REV4(c)];
    __syncwarp();
    #pragma unroll
    for (int m = 0; m < 16; m++) v[m] = xch[row][t + 8*m];
    __syncwarp();

    // (g) inverse FFT along x, write g_C (all 32 rows store)
    fft128_16<1>(v, t, xch[row], 1);
    #pragma unroll
    for (int c = 0; c < 16; c++) g_C[obase + (8*c + rt) * 16384] = v[REV4(c)];
}

// ============================================================================
// Pipeline kernels
// ============================================================================

__global__ void k_init(){
    int i = blockIdx.x * 1024 + threadIdx.x;
    float4 z4 = make_float4(0.f, 0.f, 0.f, 0.f);
    if (i < 1048576) g_b_wv[i] = z4;
    else             g_b_vzr[i - 1048576] = z4;
    if (i < 4)       g_stats[i] = 0.0;
}

__device__ __forceinline__ void corners(float px, float py, float pz,
                                        int ix[2], int iy[2], int iz[2],
                                        float wx[2], float wy[2], float wz[2]){
    float prx = px * 128.0f, pry = py * 128.0f, prz = pz * 128.0f;
    float lox = floorf(prx), loy = floorf(pry), loz = floorf(prz);
    ix[0] = ((int)lox) & 127;  iy[0] = ((int)loy) & 127;  iz[0] = ((int)loz) & 127;
    ix[1] = ((int)ceilf(prx)) & 127;
    iy[1] = ((int)ceilf(pry)) & 127;
    iz[1] = ((int)ceilf(prz)) & 127;
    float fx = prx - lox, fy = pry - loy, fz = prz - loz;
    wx[0] = 1.0f - fx; wx[1] = fx;
    wy[0] = 1.0f - fy; wy[1] = fy;
    wz[0] = 1.0f - fz; wz[1] = fz;
}

__global__ void k_scatter(const float* __restrict__ pts,
                          const float* __restrict__ nrm, int N){
    int n = blockIdx.x * 256 + threadIdx.x;
    if (n >= N) return;
    float px = pts[3*n], py = pts[3*n+1], pz = pts[3*n+2];
    float nx = nrm[3*n], ny = nrm[3*n+1], nz = nrm[3*n+2];
    int ix[2], iy[2], iz[2]; float wx[2], wy[2], wz[2];
    corners(px, py, pz, ix, iy, iz, wx, wy, wz);
    #pragma unroll
    for (int c = 0; c < 8; c++){
        int a = (c >> 2) & 1, b = (c >> 1) & 1, d = c & 1;
        float w = wx[a] * wy[b] * wz[d];
        int idx = (ix[a] << 14) | (iy[b] << 7) | iz[d];
        atomicAdd(&g_wv[idx], make_float2(w * nx, w * ny));  // vector RED (sm_90+)
        atomicAdd(&g_vzr[idx], w * nz);
    }
}

__global__ void k_interp(const float* __restrict__ pts, int N){
    int n = blockIdx.x * 256 + threadIdx.x;
    float acc = 0.0f;
    if (n < N){
        float px = pts[3*n], py = pts[3*n+1], pz = pts[3*n+2];
        int ix[2], iy[2], iz[2]; float wx[2], wy[2], wz[2];
        corners(px, py, pz, ix, iy, iz, wx, wy, wz);
        #pragma unroll
        for (int c = 0; c < 8; c++){
            int a = (c >> 2) & 1, b = (c >> 1) & 1, d = c & 1;
            float w = wx[a] * wy[b] * wz[d];
            int idx = (ix[a] << 14) | (iy[b] << 7) | iz[d];
            acc += w * g_chi[idx];
        }
    }
    #pragma unroll
    for (int o = 16; o > 0; o >>= 1)
        acc += __shfl_down_sync(0xffffffffu, acc, o);
    __shared__ float wsum[8];
    if ((threadIdx.x & 31) == 0) wsum[threadIdx.x >> 5] = acc;
    __syncthreads();
    if (threadIdx.x == 0){
        float s = 0.0f;
        #pragma unroll
        for (int i = 0; i < 8; i++) s += wsum[i];
        atomicAdd(&g_stats[0], (double)s);
    }
}

__global__ void k_finalize(int N){
    double mean = g_stats[0] / (double)N;
    double chi0 = (double)g_chi[0] - mean;
    g_stats[1] = mean;
    g_stats[2] = 0.5 / fabs(chi0);
}

__global__ void k_writeout(float4* __restrict__ out){
    int i = blockIdx.x * 256 + threadIdx.x;   // over M3/4
    float mean = (float)g_stats[1];
    float sc   = (float)g_stats[2];
    float4 c = g_b_chi[i];
    out[i] = make_float4(sc*(c.x-mean), sc*(c.y-mean), sc*(c.z-mean), sc*(c.w-mean));
}

// ============================================================================
// launch
// ============================================================================
extern "C" void kernel_launch(void* const* d_in, const int* in_sizes, int n_in,
                              void* d_out, int out_size){
    const float* pts = (const float*)d_in[0];
    const float* nrm = (const float*)d_in[1];
    const int N = in_sizes[0] / 3;

    cudaFuncSetAttribute(k_plane_zy_fwd, cudaFuncAttributeMaxDynamicSharedMemorySize,
                         (int)PLANE_BYTES);
    cudaFuncSetAttribute(k_plane_yz_inv, cudaFuncAttributeMaxDynamicSharedMemorySize,
                         (int)PLANE_BYTES);

    k_init<<<1536, 1024>>>();
    k_scatter<<<(N + 255) / 256, 256>>>(pts, nrm, N);
    // forward: 128 wv-plane blocks + 64 packed vz-pair blocks
    k_plane_zy_fwd<<<192, 1024, PLANE_BYTES>>>();
    // mirror-paired fused x-phase (Vz shared via Hermitian symmetry)
    k_x_fused<<<dim3(8, 65), 256>>>();
    // inverse: fused kz+ky per plane (full)
    k_plane_yz_inv<<<128, 1024, PLANE_BYTES>>>();
    // gather, normalize, write
    k_interp<<<(N + 255) / 256, 256>>>(pts, N);
    k_finalize<<<1, 1>>>(N);
    k_writeout<<<2048, 256>>>((float4*)d_out);
}

// round 16
// speedup vs baseline: 1.2632x; 1.0906x over previous
#include <cuda_runtime.h>

// ============================================================================
// DPSR: trilinear scatter -> 3D FFT -> spectral Poisson -> iFFT -> gather/norm
// res = 128, sigma = 2, eps = 1e-6, B = 1, N = 250000, F = 3
//
// Round 16: exact Hermitianized spectral operator
//   chi_H(k) = -i*s(k)*Sum_d utilde_d V_d(k),  utilde zeroed at Nyquist,
// computed point-locally (no mirror pairing). All fields real -> plane-paired
// z+y FFTs storing true spectra for ky<=64 only; barrier-free per-line
// x-phase; Hermitian-reconstructing yz inverse.
// ============================================================================

#define M3   2097152           // 128^3
#define FPI  3.14159265358979f
#define TP   130               // plane tile pitch in float2
#define PLANE_BYTES (128 * TP * sizeof(float2))
#define NSP  8320              // 65*128: spectrum plane size (ky<=64)
#define FSTRIDE (128 * NSP)    // per-field spectrum size

// ---- scratch (device globals; no allocation allowed) ----
__device__ float4 g_b_vxy[M3/2];        // scattered (vx,vy) interleaved (16MB)
__device__ float4 g_b_vz [M3/4];        // scattered vz (8MB)
__device__ float2 g_V[3 * FSTRIDE];     // true spectra Vx,Vy,Vz; ky<=64 (25.5MB)
__device__ float2 g_C[FSTRIDE];         // chi_H after x-inverse; ky<=64 (8.5MB)
__device__ float4 g_b_chi[M3/4];        // chi_prime (8MB)
__device__ double g_stats[4];

#define g_vxy ((float2*)g_b_vxy)
#define g_vzr ((float*)g_b_vz)
#define g_chi ((float*)g_b_chi)

__device__ __forceinline__ float2 cadd(float2 a, float2 b){ return make_float2(a.x+b.x, a.y+b.y); }
__device__ __forceinline__ float2 csub(float2 a, float2 b){ return make_float2(a.x-b.x, a.y-b.y); }
__device__ __forceinline__ float2 cmul(float2 a, float2 b){
    return make_float2(a.x*b.x - a.y*b.y, a.x*b.y + a.y*b.x);
}

#define SWX(p) ((p) ^ ((((p) >> 4) & 7)))
#define XPITCH 136

__device__ __forceinline__ int rev3i(int t){
    return ((t & 1) << 2) | (t & 2) | ((t >> 2) & 1);
}
#define REV4(c) ((((c)&1)<<3) | (((c)&2)<<1) | (((c)&4)>>1) | (((c)&8)>>3))

// ============================================================================
// 128-pt radix-2 DIF FFT: 8 threads/line, 16 values/thread (p = t + 8m).
// Exchange buffer: xbase[SWX(p)*xs]. On return v[j] = result at p = 16t+j;
// true index k = 8*rev4(j)+rev3(t). Ends with __syncwarp (buffer reusable).
// ============================================================================
template<int DIR>
__device__ __forceinline__ void fft128_16(float2 v[16], const int t,
                                          float2* __restrict__ xbase, const int xs){
    const float D  = (float)DIR;
    const float SQ = 0.70710678118654752f;
    const float2 c8 = make_float2(0.92387953251128675f, D * 0.38268343236508977f);
    const float2 c4 = make_float2(SQ, D * SQ);

    float s, c;
    __sincosf(D * (FPI / 64.0f) * (float)t, &s, &c);
    const float2 wt  = make_float2(c, s);
    const float2 w2t = cmul(wt,  wt);
    const float2 w4t = cmul(w2t, w2t);
    const float2 w8t = cmul(w4t, w4t);

    // h=64
    {
        float2 w = wt;
        #pragma unroll
        for (int m = 0; m < 8; m++){
            float2 a = v[m], b = v[m+8];
            v[m]   = cadd(a, b);
            v[m+8] = cmul(csub(a, b), w);
            w = cmul(w, c8);
        }
    }
    // h=32
    {
        float2 w = w2t;
        #pragma unroll
        for (int q = 0; q < 4; q++){
            float2 a = v[q],   b = v[q+4];
            v[q]    = cadd(a, b);  v[q+4]  = cmul(csub(a, b), w);
            a = v[8+q]; b = v[12+q];
            v[8+q]  = cadd(a, b);  v[12+q] = cmul(csub(a, b), w);
            w = cmul(w, c4);
        }
    }
    // h=16
    {
        const float2 wa = w4t;
        const float2 wb = make_float2(-D * w4t.y, D * w4t.x);
        #pragma unroll
        for (int g = 0; g < 16; g += 4){
            float2 a = v[g],   b = v[g+2];
            v[g]   = cadd(a, b);  v[g+2] = cmul(csub(a, b), wa);
            a = v[g+1]; b = v[g+3];
            v[g+1] = cadd(a, b);  v[g+3] = cmul(csub(a, b), wb);
        }
    }
    // h=8
    {
        #pragma unroll
        for (int m = 0; m < 16; m += 2){
            float2 a = v[m], b = v[m+1];
            v[m]   = cadd(a, b);
            v[m+1] = cmul(csub(a, b), w8t);
        }
    }

    // exchange: re-own 16 consecutive positions [16t..16t+15]
    #pragma unroll
    for (int m = 0; m < 16; m++) xbase[SWX(t + 8*m) * xs] = v[m];
    __syncwarp();
    #pragma unroll
    for (int j = 0; j < 16; j++) v[j] = xbase[SWX(16*t + j) * xs];
    __syncwarp();   // callers may overwrite the buffer after return

    // h=4
    {
        const float2 w2 = make_float2(0.0f, D);
        const float2 w3 = make_float2(-SQ, D * SQ);
        #pragma unroll
        for (int g = 0; g < 16; g += 8){
            float2 a, b;
            a = v[g+0]; b = v[g+4]; v[g+0] = cadd(a,b); v[g+4] = csub(a,b);
            a = v[g+1]; b = v[g+5]; v[g+1] = cadd(a,b); v[g+5] = cmul(csub(a,b), c4);
            a = v[g+2]; b = v[g+6]; v[g+2] = cadd(a,b); v[g+6] = cmul(csub(a,b), w2);
            a = v[g+3]; b = v[g+7]; v[g+3] = cadd(a,b); v[g+7] = cmul(csub(a,b), w3);
        }
    }
    // h=2
    {
        #pragma unroll
        for (int g = 0; g < 16; g += 4){
            float2 a, b, d0;
            a = v[g+0]; b = v[g+2]; v[g+0] = cadd(a,b); v[g+2] = csub(a,b);
            a = v[g+1]; b = v[g+3]; v[g+1] = cadd(a,b);
            d0 = csub(a,b);
            v[g+3] = make_float2(-D * d0.y, D * d0.x);
        }
    }
    // h=1
    {
        #pragma unroll
        for (int g = 0; g < 16; g += 2){
            float2 a = v[g], b = v[g+1];
            v[g]   = cadd(a, b);
            v[g+1] = csub(a, b);
        }
    }
}

// ============================================================================
// Forward z+y plane kernel, all fields real + plane-paired.
// Block bid: field f = bid/64 (0=vx,1=vy,2=vz), planes x1 = bid%64, x2 = x1+64
// packed as P = f(x1) + i*f(x2). After z+y FFT the full plane spectrum sits
// in the tile; Hermitian unpack stores TRUE spectra for ky<=64 into g_V.
// ============================================================================
__global__ void __launch_bounds__(1024, 1) k_plane_zy_fwd(){
    extern __shared__ float2 tile[];   // 128 * TP
    const int lane = threadIdx.x & 31;
    const int w    = threadIdx.x >> 5;
    const int t    = lane & 7;
    const int sub  = lane >> 3;
    const int yline = (w & 3) + ((w >> 2) << 4) + (sub << 2);
    const int zline = (w << 2) + sub;
    const int f    = blockIdx.x >> 6;          // 0,1,2
    const int x1   = blockIdx.x & 63;
    const int x2   = x1 + 64;
    const int p1   = x1 << 14, p2 = x2 << 14;

    float2 v[16];
    if (f == 0){
        #pragma unroll
        for (int m = 0; m < 16; m++)
            v[m] = make_float2(g_vxy[p1 + yline*128 + t + 8*m].x,
                               g_vxy[p2 + yline*128 + t + 8*m].x);
    } else if (f == 1){
        #pragma unroll
        for (int m = 0; m < 16; m++)
            v[m] = make_float2(g_vxy[p1 + yline*128 + t + 8*m].y,
                               g_vxy[p2 + yline*128 + t + 8*m].y);
    } else {
        #pragma unroll
        for (int m = 0; m < 16; m++)
            v[m] = make_float2(g_vzr[p1 + yline*128 + t + 8*m],
                               g_vzr[p2 + yline*128 + t + 8*m]);
    }
    fft128_16<-1>(v, t, tile + yline*TP, 1);
    {
        const int rt = rev3i(t);
        #pragma unroll
        for (int c = 0; c < 16; c++) tile[yline*TP + 8*c + rt] = v[REV4(c)];
    }
    __syncthreads();
    #pragma unroll
    for (int m = 0; m < 16; m++) v[m] = tile[(t + 8*m)*TP + zline];
    fft128_16<-1>(v, t, tile + zline, TP);
    {
        // park y-FFT results into own column (position = ky)
        const int rt = rev3i(t);
        #pragma unroll
        for (int c = 0; c < 16; c++)
            tile[(8*c + rt)*TP + zline] = v[REV4(c)];
    }
    __syncthreads();
    // Hermitian unpack: V1 = (A + conj(Bm))/2, V2 = -i*(A - conj(Bm))/2
    {
        float2* out1 = g_V + f*FSTRIDE + x1*NSP;
        float2* out2 = g_V + f*FSTRIDE + x2*NSP;
        for (int i = threadIdx.x; i < NSP; i += 1024){
            int ky = i >> 7, kz = i & 127;
            float2 A  = tile[ky * TP + kz];
            float2 Bm = tile[((128 - ky) & 127) * TP + ((128 - kz) & 127)];
            out1[i] = make_float2(0.5f * (A.x + Bm.x), 0.5f * (A.y - Bm.y));
            out2[i] = make_float2(0.5f * (A.y + Bm.y), -0.5f * (A.x - Bm.x));
        }
    }
}

// ============================================================================
// Barrier-free x-phase: per (ky<=64, kz) line, FFT Vz/Vy/Vx along x,
// combine chi_H(k) = s(k) * Sum utilde_d * (-i V_d), inverse FFT, store g_C.
// 128 threads = 16 independent rows; only __syncwarp inside the FFT.
// ============================================================================
__global__ void __launch_bounds__(128, 5) k_x_line(){
    __shared__ float2 xch[16][XPITCH];
    __shared__ float  sS [16][XPITCH];
    const int t    = threadIdx.x & 7;
    const int row  = threadIdx.x >> 3;
    const int rt   = rev3i(t);
    const int L    = blockIdx.x * 16 + row;      // 0..8319
    const int ky   = L >> 7;                     // 0..64
    const int kz   = L & 127;

    const float uy  = (ky == 64) ? -64.0f : (float)ky;
    const float uty = (ky == 64) ? 0.0f   : (float)ky;
    const float uzf = (kz < 64) ? (float)kz : (float)(kz - 128);
    const float utz = (kz == 64) ? 0.0f : uzf;

    float2 v[16], acc[16];

    // ---- Vz: FFT + init acc, cache s ----
    #pragma unroll
    for (int m = 0; m < 16; m++) v[m] = g_V[2*FSTRIDE + L + (t + 8*m)*NSP];
    fft128_16<-1>(v, t, xch[row], 1);
    #pragma unroll
    for (int j = 0; j < 16; j++){
        const int k = 8 * REV4(j) + rt;
        float ux = (k < 64) ? (float)k : (float)(k - 128);
        float us = ux*ux + uy*uy + uzf*uzf;
        float gk = __expf(-us * (1.0f / 2048.0f));
        float s  = gk / (2.0f * FPI * (us + 1e-6f));
        sS[row][k] = s;
        float su = s * utz;
        acc[j] = make_float2(su * v[j].y, -su * v[j].x);
    }

    // ---- Vy: FFT + accumulate ----
    #pragma unroll
    for (int m = 0; m < 16; m++) v[m] = g_V[1*FSTRIDE + L + (t + 8*m)*NSP];
    fft128_16<-1>(v, t, xch[row], 1);
    #pragma unroll
    for (int j = 0; j < 16; j++){
        const int k = 8 * REV4(j) + rt;
        float su = sS[row][k] * uty;
        acc[j].x += su * v[j].y;
        acc[j].y -= su * v[j].x;
    }

    // ---- Vx: FFT + accumulate (utx per k) ----
    #pragma unroll
    for (int m = 0; m < 16; m++) v[m] = g_V[0*FSTRIDE + L + (t + 8*m)*NSP];
    fft128_16<-1>(v, t, xch[row], 1);
    #pragma unroll
    for (int j = 0; j < 16; j++){
        const int k = 8 * REV4(j) + rt;
        float utx = (k == 64) ? 0.0f : ((k < 64) ? (float)k : (float)(k - 128));
        float su = sS[row][k] * utx;
        acc[j].x += su * v[j].y;
        acc[j].y -= su * v[j].x;
    }

    // ---- reorder chi_H from k-order to position order ----
    #pragma unroll
    for (int c = 0; c < 16; c++) xch[row][8*c + rt] = acc[REV4(c)];
    __syncwarp();
    #pragma unroll
    for (int m = 0; m < 16; m++) v[m] = xch[row][t + 8*m];
    __syncwarp();

    // ---- inverse FFT along x, store g_C (ky<=64 layout) ----
    fft128_16<1>(v, t, xch[row], 1);
    #pragma unroll
    for (int c = 0; c < 16; c++) g_C[L + (8*c + rt)*NSP] = v[REV4(c)];
}

// ============================================================================
// Inverse kz+ky plane kernel with EXACT Hermitian reconstruction (chi_H is
// Hermitian by construction). Pass 1: kz-inverse for ky<=64 (predicated
// loads keep the fft's syncwarp convergent). Pass 2: ky-inverse with
// conjugate-mirror reads for ky>64. Writes real g_chi (scaled).
// ============================================================================
__global__ void __launch_bounds__(1024, 1) k_plane_yz_inv(){
    extern __shared__ float2 tile[];   // 128 * TP
    const int lane = threadIdx.x & 31;
    const int w    = threadIdx.x >> 5;
    const int t    = lane & 7;
    const int sub  = lane >> 3;
    const int yline = (w & 3) + ((w >> 2) << 4) + (sub << 2);
    const int zline = (w << 2) + sub;
    const int x    = blockIdx.x;

    float2 v[16];
    // pass 1: kz-inverse for lines ky = yline <= 64 (others run on zeros,
    // park skipped — keeps warp-convergent syncwarps inside the fft)
    {
        const bool ok = (yline <= 64);
        const int base = x * NSP + yline * 128;
        #pragma unroll
        for (int m = 0; m < 16; m++)
            v[m] = ok ? g_C[base + t + 8*m] : make_float2(0.0f, 0.0f);
        fft128_16<1>(v, t, tile + yline*TP, 1);
        if (ok){
            const int rt = rev3i(t);
            #pragma unroll
            for (int c = 0; c < 16; c++) tile[yline*TP + 8*c + rt] = v[REV4(c)];
        }
    }
    __syncthreads();
    // pass 2: ky-inverse with Hermitian-extended reads
    #pragma unroll
    for (int m = 0; m < 16; m++){
        int p = t + 8*m;
        int q = (p <= 64) ? p : (128 - p);
        float2 val = tile[q*TP + zline];
        v[m] = (p <= 64) ? val : make_float2(val.x, -val.y);
    }
    fft128_16<1>(v, t, tile + zline, TP);
    {
        const float sc = 1.0f / 2097152.0f;
        const int rt = rev3i(t);
        const int plane = x << 14;
        #pragma unroll
        for (int c = 0; c < 16; c++)
            g_chi[plane + (8*c + rt)*128 + zline] = v[REV4(c)].x * sc;
    }
}

// ============================================================================
// Pipeline kernels
// ============================================================================

__global__ void k_init(){
    int i = blockIdx.x * 1024 + threadIdx.x;
    float4 z4 = make_float4(0.f, 0.f, 0.f, 0.f);
    if (i < 1048576) g_b_vxy[i] = z4;
    else             g_b_vz[i - 1048576] = z4;
    if (i < 4)       g_stats[i] = 0.0;
}

__device__ __forceinline__ void corners(float px, float py, float pz,
                                        int ix[2], int iy[2], int iz[2],
                                        float wx[2], float wy[2], float wz[2]){
    float prx = px * 128.0f, pry = py * 128.0f, prz = pz * 128.0f;
    float lox = floorf(prx), loy = floorf(pry), loz = floorf(prz);
    ix[0] = ((int)lox) & 127;  iy[0] = ((int)loy) & 127;  iz[0] = ((int)loz) & 127;
    ix[1] = ((int)ceilf(prx)) & 127;
    iy[1] = ((int)ceilf(pry)) & 127;
    iz[1] = ((int)ceilf(prz)) & 127;
    float fx = prx - lox, fy = pry - loy, fz = prz - loz;
    wx[0] = 1.0f - fx; wx[1] = fx;
    wy[0] = 1.0f - fy; wy[1] = fy;
    wz[0] = 1.0f - fz; wz[1] = fz;
}

__global__ void k_scatter(const float* __restrict__ pts,
                          const float* __restrict__ nrm, int N){
    int n = blockIdx.x * 256 + threadIdx.x;
    if (n >= N) return;
    float px = pts[3*n], py = pts[3*n+1], pz = pts[3*n+2];
    float nx = nrm[3*n], ny = nrm[3*n+1], nz = nrm[3*n+2];
    int ix[2], iy[2], iz[2]; float wx[2], wy[2], wz[2];
    corners(px, py, pz, ix, iy, iz, wx, wy, wz);
    #pragma unroll
    for (int c = 0; c < 8; c++){
        int a = (c >> 2) & 1, b = (c >> 1) & 1, d = c & 1;
        float w = wx[a] * wy[b] * wz[d];
        int idx = (ix[a] << 14) | (iy[b] << 7) | iz[d];
        atomicAdd(&g_vxy[idx], make_float2(w * nx, w * ny));  // vector RED
        atomicAdd(&g_vzr[idx], w * nz);
    }
}

__global__ void k_interp(const float* __restrict__ pts, int N){
    int n = blockIdx.x * 256 + threadIdx.x;
    float acc = 0.0f;
    if (n < N){
        float px = pts[3*n], py = pts[3*n+1], pz = pts[3*n+2];
        int ix[2], iy[2], iz[2]; float wx[2], wy[2], wz[2];
        corners(px, py, pz, ix, iy, iz, wx, wy, wz);
        #pragma unroll
        for (int c = 0; c < 8; c++){
            int a = (c >> 2) & 1, b = (c >> 1) & 1, d = c & 1;
            float w = wx[a] * wy[b] * wz[d];
            int idx = (ix[a] << 14) | (iy[b] << 7) | iz[d];
            acc += w * g_chi[idx];
        }
    }
    #pragma unroll
    for (int o = 16; o > 0; o >>= 1)
        acc += __shfl_down_sync(0xffffffffu, acc, o);
    __shared__ float wsum[8];
    if ((threadIdx.x & 31) == 0) wsum[threadIdx.x >> 5] = acc;
    __syncthreads();
    if (threadIdx.x == 0){
        float s = 0.0f;
        #pragma unroll
        for (int i = 0; i < 8; i++) s += wsum[i];
        atomicAdd(&g_stats[0], (double)s);
    }
}

__global__ void k_finalize(int N){
    double mean = g_stats[0] / (double)N;
    double chi0 = (double)g_chi[0] - mean;
    g_stats[1] = mean;
    g_stats[2] = 0.5 / fabs(chi0);
}

__global__ void k_writeout(float4* __restrict__ out){
    int i = blockIdx.x * 256 + threadIdx.x;   // over M3/4
    float mean = (float)g_stats[1];
    float sc   = (float)g_stats[2];
    float4 c = g_b_chi[i];
    out[i] = make_float4(sc*(c.x-mean), sc*(c.y-mean), sc*(c.z-mean), sc*(c.w-mean));
}

// ============================================================================
// launch
// ============================================================================
extern "C" void kernel_launch(void* const* d_in, const int* in_sizes, int n_in,
                              void* d_out, int out_size){
    const float* pts = (const float*)d_in[0];
    const float* nrm = (const float*)d_in[1];
    const int N = in_sizes[0] / 3;

    cudaFuncSetAttribute(k_plane_zy_fwd, cudaFuncAttributeMaxDynamicSharedMemorySize,
                         (int)PLANE_BYTES);
    cudaFuncSetAttribute(k_plane_yz_inv, cudaFuncAttributeMaxDynamicSharedMemorySize,
                         (int)PLANE_BYTES);

    k_init<<<1536, 1024>>>();
    k_scatter<<<(N + 255) / 256, 256>>>(pts, nrm, N);
    // forward: 3 fields x 64 paired-plane blocks -> true spectra (ky<=64)
    k_plane_zy_fwd<<<192, 1024, PLANE_BYTES>>>();
    // barrier-free x-phase: 8320 lines / 16 per block
    k_x_line<<<520, 128>>>();
    // inverse: Hermitian-reconstructing kz+ky planes, real output
    k_plane_yz_inv<<<128, 1024, PLANE_BYTES>>>();
    // gather, normalize, write
    k_interp<<<(N + 255) / 256, 256>>>(pts, N);
    k_finalize<<<1, 1>>>(N);
    k_writeout<<<2048, 256>>>((float4*)d_out);
}

// round 17
// speedup vs baseline: 1.2650x; 1.0014x over previous
#include <cuda_runtime.h>

// ============================================================================
// DPSR: trilinear scatter -> 3D FFT -> spectral Poisson -> iFFT -> gather/norm
// res = 128, sigma = 2, eps = 1e-6, B = 1, N = 250000, F = 3
//
// Round 17: round-16 (proven 90.8us) + ONE change: k_x_line software-pipelines
// the three field loads (double-buffered registers) so Vy/Vx strided global
// latency is fully overlapped with the previous field's FFT + combine.
// ============================================================================

#define M3   2097152           // 128^3
#define FPI  3.14159265358979f
#define TP   130               // plane tile pitch in float2
#define PLANE_BYTES (128 * TP * sizeof(float2))
#define NSP  8320              // 65*128: spectrum plane size (ky<=64)
#define FSTRIDE (128 * NSP)    // per-field spectrum size

// ---- scratch (device globals; no allocation allowed) ----
__device__ float4 g_b_vxy[M3/2];        // scattered (vx,vy) interleaved (16MB)
__device__ float4 g_b_vz [M3/4];        // scattered vz (8MB)
__device__ float2 g_V[3 * FSTRIDE];     // true spectra Vx,Vy,Vz; ky<=64 (25.5MB)
__device__ float2 g_C[FSTRIDE];         // chi_H after x-inverse; ky<=64 (8.5MB)
__device__ float4 g_b_chi[M3/4];        // chi_prime (8MB)
__device__ double g_stats[4];

#define g_vxy ((float2*)g_b_vxy)
#define g_vzr ((float*)g_b_vz)
#define g_chi ((float*)g_b_chi)

__device__ __forceinline__ float2 cadd(float2 a, float2 b){ return make_float2(a.x+b.x, a.y+b.y); }
__device__ __forceinline__ float2 csub(float2 a, float2 b){ return make_float2(a.x-b.x, a.y-b.y); }
__device__ __forceinline__ float2 cmul(float2 a, float2 b){
    return make_float2(a.x*b.x - a.y*b.y, a.x*b.y + a.y*b.x);
}

#define SWX(p) ((p) ^ ((((p) >> 4) & 7)))
#define XPITCH 136

__device__ __forceinline__ int rev3i(int t){
    return ((t & 1) << 2) | (t & 2) | ((t >> 2) & 1);
}
#define REV4(c) ((((c)&1)<<3) | (((c)&2)<<1) | (((c)&4)>>1) | (((c)&8)>>3))

// ============================================================================
// 128-pt radix-2 DIF FFT: 8 threads/line, 16 values/thread (p = t + 8m).
// Exchange buffer: xbase[SWX(p)*xs]. On return v[j] = result at p = 16t+j;
// true index k = 8*rev4(j)+rev3(t). Ends with __syncwarp (buffer reusable).
// ============================================================================
template<int DIR>
__device__ __forceinline__ void fft128_16(float2 v[16], const int t,
                                          float2* __restrict__ xbase, const int xs){
    const float D  = (float)DIR;
    const float SQ = 0.70710678118654752f;
    const float2 c8 = make_float2(0.92387953251128675f, D * 0.38268343236508977f);
    const float2 c4 = make_float2(SQ, D * SQ);

    float s, c;
    __sincosf(D * (FPI / 64.0f) * (float)t, &s, &c);
    const float2 wt  = make_float2(c, s);
    const float2 w2t = cmul(wt,  wt);
    const float2 w4t = cmul(w2t, w2t);
    const float2 w8t = cmul(w4t, w4t);

    // h=64
    {
        float2 w = wt;
        #pragma unroll
        for (int m = 0; m < 8; m++){
            float2 a = v[m], b = v[m+8];
            v[m]   = cadd(a, b);
            v[m+8] = cmul(csub(a, b), w);
            w = cmul(w, c8);
        }
    }
    // h=32
    {
        float2 w = w2t;
        #pragma unroll
        for (int q = 0; q < 4; q++){
            float2 a = v[q],   b = v[q+4];
            v[q]    = cadd(a, b);  v[q+4]  = cmul(csub(a, b), w);
            a = v[8+q]; b = v[12+q];
            v[8+q]  = cadd(a, b);  v[12+q] = cmul(csub(a, b), w);
            w = cmul(w, c4);
        }
    }
    // h=16
    {
        const float2 wa = w4t;
        const float2 wb = make_float2(-D * w4t.y, D * w4t.x);
        #pragma unroll
        for (int g = 0; g < 16; g += 4){
            float2 a = v[g],   b = v[g+2];
            v[g]   = cadd(a, b);  v[g+2] = cmul(csub(a, b), wa);
            a = v[g+1]; b = v[g+3];
            v[g+1] = cadd(a, b);  v[g+3] = cmul(csub(a, b), wb);
        }
    }
    // h=8
    {
        #pragma unroll
        for (int m = 0; m < 16; m += 2){
            float2 a = v[m], b = v[m+1];
            v[m]   = cadd(a, b);
            v[m+1] = cmul(csub(a, b), w8t);
        }
    }

    // exchange: re-own 16 consecutive positions [16t..16t+15]
    #pragma unroll
    for (int m = 0; m < 16; m++) xbase[SWX(t + 8*m) * xs] = v[m];
    __syncwarp();
    #pragma unroll
    for (int j = 0; j < 16; j++) v[j] = xbase[SWX(16*t + j) * xs];
    __syncwarp();   // callers may overwrite the buffer after return

    // h=4
    {
        const float2 w2 = make_float2(0.0f, D);
        const float2 w3 = make_float2(-SQ, D * SQ);
        #pragma unroll
        for (int g = 0; g < 16; g += 8){
            float2 a, b;
            a = v[g+0]; b = v[g+4]; v[g+0] = cadd(a,b); v[g+4] = csub(a,b);
            a = v[g+1]; b = v[g+5]; v[g+1] = cadd(a,b); v[g+5] = cmul(csub(a,b), c4);
            a = v[g+2]; b = v[g+6]; v[g+2] = cadd(a,b); v[g+6] = cmul(csub(a,b), w2);
            a = v[g+3]; b = v[g+7]; v[g+3] = cadd(a,b); v[g+7] = cmul(csub(a,b), w3);
        }
    }
    // h=2
    {
        #pragma unroll
        for (int g = 0; g < 16; g += 4){
            float2 a, b, d0;
            a = v[g+0]; b = v[g+2]; v[g+0] = cadd(a,b); v[g+2] = csub(a,b);
            a = v[g+1]; b = v[g+3]; v[g+1] = cadd(a,b);
            d0 = csub(a,b);
            v[g+3] = make_float2(-D * d0.y, D * d0.x);
        }
    }
    // h=1
    {
        #pragma unroll
        for (int g = 0; g < 16; g += 2){
            float2 a = v[g], b = v[g+1];
            v[g]   = cadd(a, b);
            v[g+1] = csub(a, b);
        }
    }
}

// ============================================================================
// Forward z+y plane kernel, all fields real + plane-paired (unchanged).
// ============================================================================
__global__ void __launch_bounds__(1024, 1) k_plane_zy_fwd(){
    extern __shared__ float2 tile[];   // 128 * TP
    const int lane = threadIdx.x & 31;
    const int w    = threadIdx.x >> 5;
    const int t    = lane & 7;
    const int sub  = lane >> 3;
    const int yline = (w & 3) + ((w >> 2) << 4) + (sub << 2);
    const int zline = (w << 2) + sub;
    const int f    = blockIdx.x >> 6;          // 0,1,2
    const int x1   = blockIdx.x & 63;
    const int x2   = x1 + 64;
    const int p1   = x1 << 14, p2 = x2 << 14;

    float2 v[16];
    if (f == 0){
        #pragma unroll
        for (int m = 0; m < 16; m++)
            v[m] = make_float2(g_vxy[p1 + yline*128 + t + 8*m].x,
                               g_vxy[p2 + yline*128 + t + 8*m].x);
    } else if (f == 1){
        #pragma unroll
        for (int m = 0; m < 16; m++)
            v[m] = make_float2(g_vxy[p1 + yline*128 + t + 8*m].y,
                               g_vxy[p2 + yline*128 + t + 8*m].y);
    } else {
        #pragma unroll
        for (int m = 0; m < 16; m++)
            v[m] = make_float2(g_vzr[p1 + yline*128 + t + 8*m],
                               g_vzr[p2 + yline*128 + t + 8*m]);
    }
    fft128_16<-1>(v, t, tile + yline*TP, 1);
    {
        const int rt = rev3i(t);
        #pragma unroll
        for (int c = 0; c < 16; c++) tile[yline*TP + 8*c + rt] = v[REV4(c)];
    }
    __syncthreads();
    #pragma unroll
    for (int m = 0; m < 16; m++) v[m] = tile[(t + 8*m)*TP + zline];
    fft128_16<-1>(v, t, tile + zline, TP);
    {
        const int rt = rev3i(t);
        #pragma unroll
        for (int c = 0; c < 16; c++)
            tile[(8*c + rt)*TP + zline] = v[REV4(c)];
    }
    __syncthreads();
    // Hermitian unpack: V1 = (A + conj(Bm))/2, V2 = -i*(A - conj(Bm))/2
    {
        float2* out1 = g_V + f*FSTRIDE + x1*NSP;
        float2* out2 = g_V + f*FSTRIDE + x2*NSP;
        for (int i = threadIdx.x; i < NSP; i += 1024){
            int ky = i >> 7, kz = i & 127;
            float2 A  = tile[ky * TP + kz];
            float2 Bm = tile[((128 - ky) & 127) * TP + ((128 - kz) & 127)];
            out1[i] = make_float2(0.5f * (A.x + Bm.x), 0.5f * (A.y - Bm.y));
            out2[i] = make_float2(0.5f * (A.y + Bm.y), -0.5f * (A.x - Bm.x));
        }
    }
}

// ============================================================================
// Barrier-free x-phase with software-pipelined field loads.
// Per (ky<=64, kz) line: FFT Vz/Vy/Vx along x (loads of field f+1 issued
// before field f's FFT), combine chi_H = s * Sum utilde_d*(-i V_d),
// inverse FFT, store g_C. 128 threads = 16 independent rows.
// ============================================================================
__global__ void __launch_bounds__(128, 4) k_x_line(){
    __shared__ float2 xch[16][XPITCH];
    __shared__ float  sS [16][XPITCH];
    const int t    = threadIdx.x & 7;
    const int row  = threadIdx.x >> 3;
    const int rt   = rev3i(t);
    const int L    = blockIdx.x * 16 + row;      // 0..8319
    const int ky   = L >> 7;                     // 0..64
    const int kz   = L & 127;

    const float uy  = (ky == 64) ? -64.0f : (float)ky;
    const float uty = (ky == 64) ? 0.0f   : (float)ky;
    const float uzf = (kz < 64) ? (float)kz : (float)(kz - 128);
    const float utz = (kz == 64) ? 0.0f : uzf;

    float2 v[16], u[16], acc[16];

    // ---- issue Vz loads, then Vy loads (both in flight) ----
    #pragma unroll
    for (int m = 0; m < 16; m++) v[m] = g_V[2*FSTRIDE + L + (t + 8*m)*NSP];
    #pragma unroll
    for (int m = 0; m < 16; m++) u[m] = g_V[1*FSTRIDE + L + (t + 8*m)*NSP];

    // ---- Vz: FFT + init acc, cache s ----
    fft128_16<-1>(v, t, xch[row], 1);
    #pragma unroll
    for (int j = 0; j < 16; j++){
        const int k = 8 * REV4(j) + rt;
        float ux = (k < 64) ? (float)k : (float)(k - 128);
        float us = ux*ux + uy*uy + uzf*uzf;
        float gk = __expf(-us * (1.0f / 2048.0f));
        float s  = gk / (2.0f * FPI * (us + 1e-6f));
        sS[row][k] = s;
        float su = s * utz;
        acc[j] = make_float2(su * v[j].y, -su * v[j].x);
    }

    // ---- issue Vx loads into (now dead) v regs ----
    #pragma unroll
    for (int m = 0; m < 16; m++) v[m] = g_V[0*FSTRIDE + L + (t + 8*m)*NSP];

    // ---- Vy: FFT + accumulate ----
    fft128_16<-1>(u, t, xch[row], 1);
    #pragma unroll
    for (int j = 0; j < 16; j++){
        const int k = 8 * REV4(j) + rt;
        float su = sS[row][k] * uty;
        acc[j].x += su * u[j].y;
        acc[j].y -= su * u[j].x;
    }

    // ---- Vx: FFT + accumulate (utx per k) ----
    fft128_16<-1>(v, t, xch[row], 1);
    #pragma unroll
    for (int j = 0; j < 16; j++){
        const int k = 8 * REV4(j) + rt;
        float utx = (k == 64) ? 0.0f : ((k < 64) ? (float)k : (float)(k - 128));
        float su = sS[row][k] * utx;
        acc[j].x += su * v[j].y;
        acc[j].y -= su * v[j].x;
    }

    // ---- reorder chi_H from k-order to position order ----
    #pragma unroll
    for (int c = 0; c < 16; c++) xch[row][8*c + rt] = acc[REV4(c)];
    __syncwarp();
    #pragma unroll
    for (int m = 0; m < 16; m++) v[m] = xch[row][t + 8*m];
    __syncwarp();

    // ---- inverse FFT along x, store g_C (ky<=64 layout) ----
    fft128_16<1>(v, t, xch[row], 1);
    #pragma unroll
    for (int c = 0; c < 16; c++) g_C[L + (8*c + rt)*NSP] = v[REV4(c)];
}

// ============================================================================
// Inverse kz+ky plane kernel with exact Hermitian reconstruction (unchanged).
// ============================================================================
__global__ void __launch_bounds__(1024, 1) k_plane_yz_inv(){
    extern __shared__ float2 tile[];   // 128 * TP
    const int lane = threadIdx.x & 31;
    const int w    = threadIdx.x >> 5;
    const int t    = lane & 7;
    const int sub  = lane >> 3;
    const int yline = (w & 3) + ((w >> 2) << 4) + (sub << 2);
    const int zline = (w << 2) + sub;
    const int x    = blockIdx.x;

    float2 v[16];
    {
        const bool ok = (yline <= 64);
        const int base = x * NSP + yline * 128;
        #pragma unroll
        for (int m = 0; m < 16; m++)
            v[m] = ok ? g_C[base + t + 8*m] : make_float2(0.0f, 0.0f);
        fft128_16<1>(v, t, tile + yline*TP, 1);
        if (ok){
            const int rt = rev3i(t);
            #pragma unroll
            for (int c = 0; c < 16; c++) tile[yline*TP + 8*c + rt] = v[REV4(c)];
        }
    }
    __syncthreads();
    #pragma unroll
    for (int m = 0; m < 16; m++){
        int p = t + 8*m;
        int q = (p <= 64) ? p : (128 - p);
        float2 val = tile[q*TP + zline];
        v[m] = (p <= 64) ? val : make_float2(val.x, -val.y);
    }
    fft128_16<1>(v, t, tile + zline, TP);
    {
        const float sc = 1.0f / 2097152.0f;
        const int rt = rev3i(t);
        const int plane = x << 14;
        #pragma unroll
        for (int c = 0; c < 16; c++)
            g_chi[plane + (8*c + rt)*128 + zline] = v[REV4(c)].x * sc;
    }
}

// ============================================================================
// Pipeline kernels (unchanged)
// ============================================================================

__global__ void k_init(){
    int i = blockIdx.x * 1024 + threadIdx.x;
    float4 z4 = make_float4(0.f, 0.f, 0.f, 0.f);
    if (i < 1048576) g_b_vxy[i] = z4;
    else             g_b_vz[i - 1048576] = z4;
    if (i < 4)       g_stats[i] = 0.0;
}

__device__ __forceinline__ void corners(float px, float py, float pz,
                                        int ix[2], int iy[2], int iz[2],
                                        float wx[2], float wy[2], float wz[2]){
    float prx = px * 128.0f, pry = py * 128.0f, prz = pz * 128.0f;
    float lox = floorf(prx), loy = floorf(pry), loz = floorf(prz);
    ix[0] = ((int)lox) & 127;  iy[0] = ((int)loy) & 127;  iz[0] = ((int)loz) & 127;
    ix[1] = ((int)ceilf(prx)) & 127;
    iy[1] = ((int)ceilf(pry)) & 127;
    iz[1] = ((int)ceilf(prz)) & 127;
    float fx = prx - lox, fy = pry - loy, fz = prz - loz;
    wx[0] = 1.0f - fx; wx[1] = fx;
    wy[0] = 1.0f - fy; wy[1] = fy;
    wz[0] = 1.0f - fz; wz[1] = fz;
}

__global__ void k_scatter(const float* __restrict__ pts,
                          const float* __restrict__ nrm, int N){
    int n = blockIdx.x * 256 + threadIdx.x;
    if (n >= N) return;
    float px = pts[3*n], py = pts[3*n+1], pz = pts[3*n+2];
    float nx = nrm[3*n], ny = nrm[3*n+1], nz = nrm[3*n+2];
    int ix[2], iy[2], iz[2]; float wx[2], wy[2], wz[2];
    corners(px, py, pz, ix, iy, iz, wx, wy, wz);
    #pragma unroll
    for (int c = 0; c < 8; c++){
        int a = (c >> 2) & 1, b = (c >> 1) & 1, d = c & 1;
        float w = wx[a] * wy[b] * wz[d];
        int idx = (ix[a] << 14) | (iy[b] << 7) | iz[d];
        atomicAdd(&g_vxy[idx], make_float2(w * nx, w * ny));  // vector RED
        atomicAdd(&g_vzr[idx], w * nz);
    }
}

__global__ void k_interp(const float* __restrict__ pts, int N){
    int n = blockIdx.x * 256 + threadIdx.x;
    float acc = 0.0f;
    if (n < N){
        float px = pts[3*n], py = pts[3*n+1], pz = pts[3*n+2];
        int ix[2], iy[2], iz[2]; float wx[2], wy[2], wz[2];
        corners(px, py, pz, ix, iy, iz, wx, wy, wz);
        #pragma unroll
        for (int c = 0; c < 8; c++){
            int a = (c >> 2) & 1, b = (c >> 1) & 1, d = c & 1;
            float w = wx[a] * wy[b] * wz[d];
            int idx = (ix[a] << 14) | (iy[b] << 7) | iz[d];
            acc += w * g_chi[idx];
        }
    }
    #pragma unroll
    for (int o = 16; o > 0; o >>= 1)
        acc += __shfl_down_sync(0xffffffffu, acc, o);
    __shared__ float wsum[8];
    if ((threadIdx.x & 31) == 0) wsum[threadIdx.x >> 5] = acc;
    __syncthreads();
    if (threadIdx.x == 0){
        float s = 0.0f;
        #pragma unroll
        for (int i = 0; i < 8; i++) s += wsum[i];
        atomicAdd(&g_stats[0], (double)s);
    }
}

__global__ void k_finalize(int N){
    double mean = g_stats[0] / (double)N;
    double chi0 = (double)g_chi[0] - mean;
    g_stats[1] = mean;
    g_stats[2] = 0.5 / fabs(chi0);
}

__global__ void k_writeout(float4* __restrict__ out){
    int i = blockIdx.x * 256 + threadIdx.x;   // over M3/4
    float mean = (float)g_stats[1];
    float sc   = (float)g_stats[2];
    float4 c = g_b_chi[i];
    out[i] = make_float4(sc*(c.x-mean), sc*(c.y-mean), sc*(c.z-mean), sc*(c.w-mean));
}

// ============================================================================
// launch
// ============================================================================
extern "C" void kernel_launch(void* const* d_in, const int* in_sizes, int n_in,
                              void* d_out, int out_size){
    const float* pts = (const float*)d_in[0];
    const float* nrm = (const float*)d_in[1];
    const int N = in_sizes[0] / 3;

    cudaFuncSetAttribute(k_plane_zy_fwd, cudaFuncAttributeMaxDynamicSharedMemorySize,
                         (int)PLANE_BYTES);
    cudaFuncSetAttribute(k_plane_yz_inv, cudaFuncAttributeMaxDynamicSharedMemorySize,
                         (int)PLANE_BYTES);

    k_init<<<1536, 1024>>>();
    k_scatter<<<(N + 255) / 256, 256>>>(pts, nrm, N);
    // forward: 3 fields x 64 paired-plane blocks -> true spectra (ky<=64)
    k_plane_zy_fwd<<<192, 1024, PLANE_BYTES>>>();
    // software-pipelined barrier-free x-phase
    k_x_line<<<520, 128>>>();
    // inverse: Hermitian-reconstructing kz+ky planes, real output
    k_plane_yz_inv<<<128, 1024, PLANE_BYTES>>>();
    // gather, normalize, write
    k_interp<<<(N + 255) / 256, 256>>>(pts, N);
    k_finalize<<<1, 1>>>(N);
    k_writeout<<<2048, 256>>>((float4*)d_out);
}